// round 2
// baseline (speedup 1.0000x reference)
#include <cuda_runtime.h>
#include <cuda_bf16.h>
#include <math.h>

// Problem constants
#define BB   16
#define CC   256
#define NN   1024
#define HID  512
#define KNN  9
#define MTOT (BB*NN)   // 16384

// GEMM tiling
#define Bb 64
#define Bn 64
#define KT 16

// ---------------- scratch (static device globals; no allocations) ----------
__device__ float g_h   [(size_t)BB*NN*CC];      // node-major h: [(b*N+n)*C + c]   16 MB
__device__ float g_x2  [BB*NN];                 // row squared norms
__device__ float g_dist[(size_t)BB*NN*NN];      // per-batch distance matrices     64 MB
__device__ int   g_idx [BB*NN*KNN];             // knn indices (batch-local)
__device__ float g_m   [(size_t)BB*NN*2*CC];    // interleaved [h, maxdiff]        32 MB
__device__ float g_g   [(size_t)BB*NN*HID];     // post-GELU activations           32 MB

// ---------------------------------------------------------------------------
// Kernel 1: h = BN1(fc1_w @ x + fc1_b), written node-major.
// A[m,k] = x[b, k, n] (m-contiguous), W[c,k] = fc1_w row-major.
__global__ void fc1_kernel(const float* __restrict__ x,
                           const float* __restrict__ w,
                           const float* __restrict__ bias,
                           const float* __restrict__ bg, const float* __restrict__ bbta,
                           const float* __restrict__ bm, const float* __restrict__ bv)
{
    __shared__ float As[KT][Bb+4];
    __shared__ float Ws[KT][Bn+4];
    const int b  = blockIdx.z;
    const int n0 = blockIdx.x * Bb;
    const int c0 = blockIdx.y * Bn;
    const int tid = threadIdx.x;
    const int tx = tid & 15, ty = tid >> 4;
    const float* xb = x + (size_t)b*CC*NN;

    float acc[4][4];
#pragma unroll
    for (int i = 0; i < 4; i++)
#pragma unroll
        for (int j = 0; j < 4; j++) acc[i][j] = 0.f;

    for (int k0 = 0; k0 < CC; k0 += KT) {
#pragma unroll
        for (int i = 0; i < 4; i++) {                 // A: mm fastest (coalesced over n)
            int e = tid + i*256;
            int mm = e & 63, kk = e >> 6;
            As[kk][mm] = xb[(size_t)(k0+kk)*NN + n0 + mm];
        }
#pragma unroll
        for (int i = 0; i < 4; i++) {                 // W: kk fastest (coalesced over k)
            int e = tid + i*256;
            int kk = e & 15, nn = e >> 4;
            Ws[kk][nn] = w[(size_t)(c0+nn)*CC + k0 + kk];
        }
        __syncthreads();
#pragma unroll
        for (int kk = 0; kk < KT; kk++) {
            float a[4], wv[4];
#pragma unroll
            for (int i = 0; i < 4; i++) a[i]  = As[kk][ty*4+i];
#pragma unroll
            for (int j = 0; j < 4; j++) wv[j] = Ws[kk][tx*4+j];
#pragma unroll
            for (int i = 0; i < 4; i++)
#pragma unroll
                for (int j = 0; j < 4; j++) acc[i][j] = fmaf(a[i], wv[j], acc[i][j]);
        }
        __syncthreads();
    }
#pragma unroll
    for (int j = 0; j < 4; j++) {
        int c = c0 + tx*4 + j;
        float sc = bg[c] * rsqrtf(bv[c] + 1e-5f);
        float sh = bbta[c] - bm[c]*sc;
        float bi = bias[c];
#pragma unroll
        for (int i = 0; i < 4; i++) {
            int n = n0 + ty*4 + i;
            g_h[((size_t)b*NN + n)*CC + c] = (acc[i][j] + bi)*sc + sh;
        }
    }
}

// ---------------------------------------------------------------------------
// Kernel 2: row squared norms of h (one warp per node).
__global__ void x2_kernel()
{
    int warp = (blockIdx.x*blockDim.x + threadIdx.x) >> 5;
    int lane = threadIdx.x & 31;
    if (warp >= MTOT) return;
    const float* r = g_h + (size_t)warp*CC;
    float s = 0.f;
    for (int c = lane; c < CC; c += 32) { float v = r[c]; s = fmaf(v, v, s); }
#pragma unroll
    for (int o = 16; o; o >>= 1) s += __shfl_xor_sync(0xffffffffu, s, o);
    if (!lane) g_x2[warp] = s;
}

// ---------------------------------------------------------------------------
// Kernel 3: dist[b][n][m] = x2[n] + x2[m] - 2 * <h_n, h_m> (per batch).
// Both operands k-contiguous node-major.
__global__ void dist_kernel()
{
    __shared__ float As[KT][Bb+4];
    __shared__ float Ws[KT][Bn+4];
    const int b  = blockIdx.z;
    const int n0 = blockIdx.x * Bb;
    const int m0 = blockIdx.y * Bn;
    const int tid = threadIdx.x;
    const int tx = tid & 15, ty = tid >> 4;
    const float* hb = g_h + (size_t)b*NN*CC;

    float acc[4][4];
#pragma unroll
    for (int i = 0; i < 4; i++)
#pragma unroll
        for (int j = 0; j < 4; j++) acc[i][j] = 0.f;

    for (int k0 = 0; k0 < CC; k0 += KT) {
#pragma unroll
        for (int i = 0; i < 4; i++) {                 // kk fastest
            int e = tid + i*256;
            int kk = e & 15, mm = e >> 4;
            As[kk][mm] = hb[(size_t)(n0+mm)*CC + k0 + kk];
        }
#pragma unroll
        for (int i = 0; i < 4; i++) {
            int e = tid + i*256;
            int kk = e & 15, nn = e >> 4;
            Ws[kk][nn] = hb[(size_t)(m0+nn)*CC + k0 + kk];
        }
        __syncthreads();
#pragma unroll
        for (int kk = 0; kk < KT; kk++) {
            float a[4], wv[4];
#pragma unroll
            for (int i = 0; i < 4; i++) a[i]  = As[kk][ty*4+i];
#pragma unroll
            for (int j = 0; j < 4; j++) wv[j] = Ws[kk][tx*4+j];
#pragma unroll
            for (int i = 0; i < 4; i++)
#pragma unroll
                for (int j = 0; j < 4; j++) acc[i][j] = fmaf(a[i], wv[j], acc[i][j]);
        }
        __syncthreads();
    }
    float* db = g_dist + (size_t)b*NN*NN;
    float xm[4];
#pragma unroll
    for (int j = 0; j < 4; j++) xm[j] = g_x2[b*NN + m0 + tx*4 + j];
#pragma unroll
    for (int i = 0; i < 4; i++) {
        int n = n0 + ty*4 + i;
        float xn = g_x2[b*NN + n];
#pragma unroll
        for (int j = 0; j < 4; j++) {
            int m = m0 + tx*4 + j;
            db[(size_t)n*NN + m] = xn + xm[j] - 2.f*acc[i][j];
        }
    }
}

// ---------------------------------------------------------------------------
// Kernel 4: top-9 smallest per distance row (tie -> lower index).
__global__ void topk_kernel()
{
    const int row = blockIdx.x;            // b*N + n
    const float* d = g_dist + (size_t)row * NN;
    __shared__ float sd[NN];
    __shared__ float rv[256];
    __shared__ int   ri[256];
    const int t = threadIdx.x;             // 256 threads
    for (int i = t; i < NN; i += 256) sd[i] = d[i];
    __syncthreads();
    for (int kp = 0; kp < KNN; kp++) {
        float bv = INFINITY; int bi = NN;
        for (int i = t; i < NN; i += 256) {
            float v = sd[i];
            if (v < bv) { bv = v; bi = i; }   // strict < keeps earliest index
        }
        rv[t] = bv; ri[t] = bi;
        __syncthreads();
        for (int s = 128; s > 0; s >>= 1) {
            if (t < s) {
                float ov = rv[t+s]; int oi = ri[t+s];
                if (ov < rv[t] || (ov == rv[t] && oi < ri[t])) { rv[t] = ov; ri[t] = oi; }
            }
            __syncthreads();
        }
        if (t == 0) {
            g_idx[row*KNN + kp] = ri[0];
            sd[ri[0]] = INFINITY;
        }
        __syncthreads();
    }
}

// ---------------------------------------------------------------------------
// Kernel 5: MRConv + interleave: m[2c]=h[c], m[2c+1]=max_j(h[idx_j,c]-h[n,c])
__global__ void mrconv_kernel()
{
    const int n = blockIdx.x, b = blockIdx.y, c = threadIdx.x;  // 256 threads
    const size_t rowb = (size_t)b*NN + n;
    __shared__ int sidx[KNN];
    if (c < KNN) sidx[c] = g_idx[rowb*KNN + c];
    __syncthreads();
    float v = g_h[rowb*CC + c];
    float mx = -INFINITY;
#pragma unroll
    for (int j = 0; j < KNN; j++) {
        int nb = sidx[j];
        mx = fmaxf(mx, g_h[((size_t)b*NN + nb)*CC + c] - v);
    }
    float* mo = g_m + rowb*2*CC;
    mo[2*c]   = v;
    mo[2*c+1] = mx;
}

// ---------------------------------------------------------------------------
// Kernel 6: g = GELU(BN2(GBN(gc_w @ m + gc_b)))
__global__ void gc_kernel(const float* __restrict__ w, const float* __restrict__ bias,
                          const float* __restrict__ g1g, const float* __restrict__ g1b,
                          const float* __restrict__ g1m, const float* __restrict__ g1v,
                          const float* __restrict__ g2g, const float* __restrict__ g2b,
                          const float* __restrict__ g2m, const float* __restrict__ g2v)
{
    __shared__ float As[KT][Bb+4];
    __shared__ float Ws[KT][Bn+4];
    const int r0 = blockIdx.x * Bb;     // global row in [0, 16384)
    const int c0 = blockIdx.y * Bn;
    const int tid = threadIdx.x;
    const int tx = tid & 15, ty = tid >> 4;

    float acc[4][4];
#pragma unroll
    for (int i = 0; i < 4; i++)
#pragma unroll
        for (int j = 0; j < 4; j++) acc[i][j] = 0.f;

    for (int k0 = 0; k0 < 2*CC; k0 += KT) {
#pragma unroll
        for (int i = 0; i < 4; i++) {
            int e = tid + i*256;
            int kk = e & 15, mm = e >> 4;
            As[kk][mm] = g_m[(size_t)(r0+mm)*2*CC + k0 + kk];
        }
#pragma unroll
        for (int i = 0; i < 4; i++) {
            int e = tid + i*256;
            int kk = e & 15, nn = e >> 4;
            Ws[kk][nn] = w[(size_t)(c0+nn)*2*CC + k0 + kk];
        }
        __syncthreads();
#pragma unroll
        for (int kk = 0; kk < KT; kk++) {
            float a[4], wv[4];
#pragma unroll
            for (int i = 0; i < 4; i++) a[i]  = As[kk][ty*4+i];
#pragma unroll
            for (int j = 0; j < 4; j++) wv[j] = Ws[kk][tx*4+j];
#pragma unroll
            for (int i = 0; i < 4; i++)
#pragma unroll
                for (int j = 0; j < 4; j++) acc[i][j] = fmaf(a[i], wv[j], acc[i][j]);
        }
        __syncthreads();
    }
#pragma unroll
    for (int j = 0; j < 4; j++) {
        int c = c0 + tx*4 + j;
        float s1 = g1g[c] * rsqrtf(g1v[c] + 1e-5f);
        float t1 = g1b[c] - g1m[c]*s1;
        float s2 = g2g[c] * rsqrtf(g2v[c] + 1e-5f);
        float t2 = g2b[c] - g2m[c]*s2;
        float bi = bias[c];
#pragma unroll
        for (int i = 0; i < 4; i++) {
            float y = ((acc[i][j] + bi)*s1 + t1)*s2 + t2;
            y = 0.5f * y * (1.f + erff(y * 0.70710678118654752440f));
            g_g[(size_t)(r0 + ty*4 + i)*HID + c] = y;
        }
    }
}

// ---------------------------------------------------------------------------
// Kernel 7: out = BN3(fc2_w @ g + fc2_b) + x, written (B,C,N) with coalesced
// transposed stores staged through shared memory.
__global__ void fc2_kernel(const float* __restrict__ w, const float* __restrict__ bias,
                           const float* __restrict__ bg, const float* __restrict__ bbta,
                           const float* __restrict__ bm, const float* __restrict__ bv,
                           const float* __restrict__ x, float* __restrict__ out)
{
    __shared__ float As[KT][Bb+4];
    __shared__ float Ws[KT][Bn+4];
    __shared__ float Os[Bb][Bn+1];
    const int r0 = blockIdx.x * Bb;
    const int c0 = blockIdx.y * Bn;
    const int tid = threadIdx.x;
    const int tx = tid & 15, ty = tid >> 4;

    float acc[4][4];
#pragma unroll
    for (int i = 0; i < 4; i++)
#pragma unroll
        for (int j = 0; j < 4; j++) acc[i][j] = 0.f;

    for (int k0 = 0; k0 < HID; k0 += KT) {
#pragma unroll
        for (int i = 0; i < 4; i++) {
            int e = tid + i*256;
            int kk = e & 15, mm = e >> 4;
            As[kk][mm] = g_g[(size_t)(r0+mm)*HID + k0 + kk];
        }
#pragma unroll
        for (int i = 0; i < 4; i++) {
            int e = tid + i*256;
            int kk = e & 15, nn = e >> 4;
            Ws[kk][nn] = w[(size_t)(c0+nn)*HID + k0 + kk];
        }
        __syncthreads();
#pragma unroll
        for (int kk = 0; kk < KT; kk++) {
            float a[4], wv[4];
#pragma unroll
            for (int i = 0; i < 4; i++) a[i]  = As[kk][ty*4+i];
#pragma unroll
            for (int j = 0; j < 4; j++) wv[j] = Ws[kk][tx*4+j];
#pragma unroll
            for (int i = 0; i < 4; i++)
#pragma unroll
                for (int j = 0; j < 4; j++) acc[i][j] = fmaf(a[i], wv[j], acc[i][j]);
        }
        __syncthreads();
    }
#pragma unroll
    for (int j = 0; j < 4; j++) {
        int c = c0 + tx*4 + j;
        float sc = bg[c] * rsqrtf(bv[c] + 1e-5f);
        float sh = bbta[c] - bm[c]*sc;
        float bi = bias[c];
#pragma unroll
        for (int i = 0; i < 4; i++) {
            Os[ty*4 + i][tx*4 + j] = (acc[i][j] + bi)*sc + sh;
        }
    }
    __syncthreads();
    const int b = r0 >> 10;
    const int nbase = r0 & 1023;
#pragma unroll
    for (int it = 0; it < 16; it++) {
        int e = tid + it*256;
        int nl = e & 63;          // local n (fastest -> coalesced)
        int cl = e >> 6;          // local c
        size_t o = (size_t)b*CC*NN + (size_t)(c0 + cl)*NN + (nbase + nl);
        out[o] = Os[nl][cl] + x[o];
    }
}

// ---------------------------------------------------------------------------
extern "C" void kernel_launch(void* const* d_in, const int* in_sizes, int n_in,
                              void* d_out, int out_size)
{
    const float* x     = (const float*)d_in[0];
    const float* fc1_w = (const float*)d_in[1];
    const float* fc1_b = (const float*)d_in[2];
    const float* bn1_g = (const float*)d_in[3];
    const float* bn1_b = (const float*)d_in[4];
    const float* bn1_m = (const float*)d_in[5];
    const float* bn1_v = (const float*)d_in[6];
    const float* gc_w  = (const float*)d_in[7];
    const float* gc_b  = (const float*)d_in[8];
    const float* gbn_g = (const float*)d_in[9];
    const float* gbn_b = (const float*)d_in[10];
    const float* gbn_m = (const float*)d_in[11];
    const float* gbn_v = (const float*)d_in[12];
    const float* bn2_g = (const float*)d_in[13];
    const float* bn2_b = (const float*)d_in[14];
    const float* bn2_m = (const float*)d_in[15];
    const float* bn2_v = (const float*)d_in[16];
    const float* fc2_w = (const float*)d_in[17];
    const float* fc2_b = (const float*)d_in[18];
    const float* bn3_g = (const float*)d_in[19];
    const float* bn3_b = (const float*)d_in[20];
    const float* bn3_m = (const float*)d_in[21];
    const float* bn3_v = (const float*)d_in[22];
    float* out = (float*)d_out;

    // 1) fc1 + BN1 -> h (node-major)
    {
        dim3 grid(NN/Bb, CC/Bn, BB);
        fc1_kernel<<<grid, 256>>>(x, fc1_w, fc1_b, bn1_g, bn1_b, bn1_m, bn1_v);
    }
    // 2) row norms
    x2_kernel<<<(MTOT*32)/256, 256>>>();
    // 3) pairwise distances
    {
        dim3 grid(NN/Bb, NN/Bn, BB);
        dist_kernel<<<grid, 256>>>();
    }
    // 4) top-9 nearest per node
    topk_kernel<<<MTOT, 256>>>();
    // 5) MRConv + interleave
    {
        dim3 grid(NN, BB);
        mrconv_kernel<<<grid, 256>>>();
    }
    // 6) gc + gbn + bn2 + GELU
    {
        dim3 grid(MTOT/Bb, HID/Bn);
        gc_kernel<<<grid, 256>>>(gc_w, gc_b, gbn_g, gbn_b, gbn_m, gbn_v,
                                 bn2_g, bn2_b, bn2_m, bn2_v);
    }
    // 7) fc2 + bn3 + residual
    {
        dim3 grid(MTOT/Bb, CC/Bn);
        fc2_kernel<<<grid, 256>>>(fc2_w, fc2_b, bn3_g, bn3_b, bn3_m, bn3_v, x, out);
    }
}

// round 4
// speedup vs baseline: 1.5408x; 1.5408x over previous
#include <cuda_runtime.h>
#include <cuda_bf16.h>
#include <stdint.h>
#include <math.h>

// Problem constants
#define BB   16
#define CC   256
#define NN   1024
#define HID  512
#define KNN  9
#define MTOT (BB*NN)   // 16384

// FFMA GEMM tiling (fc1, dist)
#define Bb 64
#define Bn 64
#define KT 16

// tf32 GEMM smem strides (words); both ≡ 4 (mod 32) for conflict-free frag loads
#define SA 132   // 128 + 4
#define SB 68    // 64 + 4

// ---------------- scratch (static device globals; no allocations) ----------
__device__ float g_h   [(size_t)BB*NN*CC];      // node-major h: [(b*N+n)*C + c]
__device__ float g_x2  [BB*NN];                 // row squared norms
__device__ float g_dist[(size_t)BB*NN*NN];      // per-batch distance matrices
__device__ int   g_idx [BB*NN*KNN];             // knn indices (batch-local)
__device__ float g_m   [(size_t)BB*NN*2*CC];    // interleaved [h, maxdiff]
__device__ float g_g   [(size_t)BB*NN*HID];     // post-GELU activations

// ---------------------------------------------------------------------------
// tf32 helpers
__device__ __forceinline__ uint32_t f2tf32(float f){
    uint32_t u; asm("cvt.rna.tf32.f32 %0, %1;" : "=r"(u) : "f"(f)); return u;
}
__device__ __forceinline__ void mma_tf32(float* c,
    uint32_t a0, uint32_t a1, uint32_t a2, uint32_t a3, uint32_t b0, uint32_t b1)
{
    asm volatile("mma.sync.aligned.m16n8k8.row.col.f32.tf32.tf32.f32 "
        "{%0,%1,%2,%3}, {%4,%5,%6,%7}, {%8,%9}, {%0,%1,%2,%3};"
        : "+f"(c[0]), "+f"(c[1]), "+f"(c[2]), "+f"(c[3])
        : "r"(a0), "r"(a1), "r"(a2), "r"(a3), "r"(b0), "r"(b1));
}

// tf32 GEMM core: block tile 128x64, 256 threads (8 warps, warp tile 32x32).
// A: row-major MxK (pre-offset to block row), B: row-major NxK (pre-offset to
// block col); both k-contiguous. Accumulates acc[mi][ni][4] in fp32.
template<int K>
__device__ __forceinline__ void tf32_gemm_tile(
    const float* __restrict__ A, const float* __restrict__ B,
    uint32_t* Ask, uint32_t* Bsk, float acc[2][4][4], int tid)
{
    const int lane = tid & 31, w = tid >> 5;
    const int gid = lane >> 2, tig = lane & 3;
    const int wm = (w & 3) * 32, wn = (w >> 2) * 32;
    const int am = tid >> 1, ak = (tid & 1) * 8;   // A loader: row, k-offset
    const int bn = tid >> 2, bk = (tid & 3) * 4;   // B loader

    for (int k0 = 0; k0 < K; k0 += 16) {
        float4 a4a = *(const float4*)(A + (size_t)am*K + k0 + ak);
        float4 a4b = *(const float4*)(A + (size_t)am*K + k0 + ak + 4);
        Ask[(ak+0)*SA + am] = f2tf32(a4a.x);
        Ask[(ak+1)*SA + am] = f2tf32(a4a.y);
        Ask[(ak+2)*SA + am] = f2tf32(a4a.z);
        Ask[(ak+3)*SA + am] = f2tf32(a4a.w);
        Ask[(ak+4)*SA + am] = f2tf32(a4b.x);
        Ask[(ak+5)*SA + am] = f2tf32(a4b.y);
        Ask[(ak+6)*SA + am] = f2tf32(a4b.z);
        Ask[(ak+7)*SA + am] = f2tf32(a4b.w);
        float4 b4 = *(const float4*)(B + (size_t)bn*K + k0 + bk);
        Bsk[(bk+0)*SB + bn] = f2tf32(b4.x);
        Bsk[(bk+1)*SB + bn] = f2tf32(b4.y);
        Bsk[(bk+2)*SB + bn] = f2tf32(b4.z);
        Bsk[(bk+3)*SB + bn] = f2tf32(b4.w);
        __syncthreads();
#pragma unroll
        for (int ks = 0; ks < 16; ks += 8) {
            uint32_t af[2][4], bf[4][2];
#pragma unroll
            for (int mi = 0; mi < 2; mi++) {
                int mo = wm + mi*16 + gid;
                af[mi][0] = Ask[(ks+tig  )*SA + mo];
                af[mi][1] = Ask[(ks+tig  )*SA + mo + 8];
                af[mi][2] = Ask[(ks+tig+4)*SA + mo];
                af[mi][3] = Ask[(ks+tig+4)*SA + mo + 8];
            }
#pragma unroll
            for (int ni = 0; ni < 4; ni++) {
                int no = wn + ni*8 + gid;
                bf[ni][0] = Bsk[(ks+tig  )*SB + no];
                bf[ni][1] = Bsk[(ks+tig+4)*SB + no];
            }
#pragma unroll
            for (int mi = 0; mi < 2; mi++)
#pragma unroll
                for (int ni = 0; ni < 4; ni++)
                    mma_tf32(acc[mi][ni], af[mi][0], af[mi][1], af[mi][2], af[mi][3],
                             bf[ni][0], bf[ni][1]);
        }
        __syncthreads();
    }
}

// ---------------------------------------------------------------------------
// Kernel 1 (FFMA, exact): h = BN1(fc1_w @ x + fc1_b), node-major output.
__global__ void fc1_kernel(const float* __restrict__ x,
                           const float* __restrict__ w,
                           const float* __restrict__ bias,
                           const float* __restrict__ bg, const float* __restrict__ bbta,
                           const float* __restrict__ bm, const float* __restrict__ bv)
{
    __shared__ float As[KT][Bb+4];
    __shared__ float Ws[KT][Bn+4];
    const int b  = blockIdx.z;
    const int n0 = blockIdx.x * Bb;
    const int c0 = blockIdx.y * Bn;
    const int tid = threadIdx.x;
    const int tx = tid & 15, ty = tid >> 4;
    const float* xb = x + (size_t)b*CC*NN;

    float acc[4][4];
#pragma unroll
    for (int i = 0; i < 4; i++)
#pragma unroll
        for (int j = 0; j < 4; j++) acc[i][j] = 0.f;

    for (int k0 = 0; k0 < CC; k0 += KT) {
#pragma unroll
        for (int i = 0; i < 4; i++) {
            int e = tid + i*256;
            int mm = e & 63, kk = e >> 6;
            As[kk][mm] = xb[(size_t)(k0+kk)*NN + n0 + mm];
        }
#pragma unroll
        for (int i = 0; i < 4; i++) {
            int e = tid + i*256;
            int kk = e & 15, nn = e >> 4;
            Ws[kk][nn] = w[(size_t)(c0+nn)*CC + k0 + kk];
        }
        __syncthreads();
#pragma unroll
        for (int kk = 0; kk < KT; kk++) {
            float a[4], wv[4];
#pragma unroll
            for (int i = 0; i < 4; i++) a[i]  = As[kk][ty*4+i];
#pragma unroll
            for (int j = 0; j < 4; j++) wv[j] = Ws[kk][tx*4+j];
#pragma unroll
            for (int i = 0; i < 4; i++)
#pragma unroll
                for (int j = 0; j < 4; j++) acc[i][j] = fmaf(a[i], wv[j], acc[i][j]);
        }
        __syncthreads();
    }
#pragma unroll
    for (int j = 0; j < 4; j++) {
        int c = c0 + tx*4 + j;
        float sc = bg[c] * rsqrtf(bv[c] + 1e-5f);
        float sh = bbta[c] - bm[c]*sc;
        float bi = bias[c];
#pragma unroll
        for (int i = 0; i < 4; i++) {
            int n = n0 + ty*4 + i;
            g_h[((size_t)b*NN + n)*CC + c] = (acc[i][j] + bi)*sc + sh;
        }
    }
}

// ---------------------------------------------------------------------------
// Kernel 2: row squared norms of h.
__global__ void x2_kernel()
{
    int warp = (blockIdx.x*blockDim.x + threadIdx.x) >> 5;
    int lane = threadIdx.x & 31;
    if (warp >= MTOT) return;
    const float* r = g_h + (size_t)warp*CC;
    float s = 0.f;
    for (int c = lane; c < CC; c += 32) { float v = r[c]; s = fmaf(v, v, s); }
#pragma unroll
    for (int o = 16; o; o >>= 1) s += __shfl_xor_sync(0xffffffffu, s, o);
    if (!lane) g_x2[warp] = s;
}

// ---------------------------------------------------------------------------
// Kernel 3 (FFMA, exact): dist[b][n][m] = x2[n] + x2[m] - 2 <h_n, h_m>.
__global__ void dist_kernel()
{
    __shared__ float As[KT][Bb+4];
    __shared__ float Ws[KT][Bn+4];
    const int b  = blockIdx.z;
    const int n0 = blockIdx.x * Bb;
    const int m0 = blockIdx.y * Bn;
    const int tid = threadIdx.x;
    const int tx = tid & 15, ty = tid >> 4;
    const float* hb = g_h + (size_t)b*NN*CC;

    float acc[4][4];
#pragma unroll
    for (int i = 0; i < 4; i++)
#pragma unroll
        for (int j = 0; j < 4; j++) acc[i][j] = 0.f;

    for (int k0 = 0; k0 < CC; k0 += KT) {
#pragma unroll
        for (int i = 0; i < 4; i++) {
            int e = tid + i*256;
            int kk = e & 15, mm = e >> 4;
            As[kk][mm] = hb[(size_t)(n0+mm)*CC + k0 + kk];
        }
#pragma unroll
        for (int i = 0; i < 4; i++) {
            int e = tid + i*256;
            int kk = e & 15, nn = e >> 4;
            Ws[kk][nn] = hb[(size_t)(m0+nn)*CC + k0 + kk];
        }
        __syncthreads();
#pragma unroll
        for (int kk = 0; kk < KT; kk++) {
            float a[4], wv[4];
#pragma unroll
            for (int i = 0; i < 4; i++) a[i]  = As[kk][ty*4+i];
#pragma unroll
            for (int j = 0; j < 4; j++) wv[j] = Ws[kk][tx*4+j];
#pragma unroll
            for (int i = 0; i < 4; i++)
#pragma unroll
                for (int j = 0; j < 4; j++) acc[i][j] = fmaf(a[i], wv[j], acc[i][j]);
        }
        __syncthreads();
    }
    float* db = g_dist + (size_t)b*NN*NN;
    float xm[4];
#pragma unroll
    for (int j = 0; j < 4; j++) xm[j] = g_x2[b*NN + m0 + tx*4 + j];
#pragma unroll
    for (int i = 0; i < 4; i++) {
        int n = n0 + ty*4 + i;
        float xn = g_x2[b*NN + n];
#pragma unroll
        for (int j = 0; j < 4; j++) {
            int m = m0 + tx*4 + j;
            db[(size_t)n*NN + m] = xn + xm[j] - 2.f*acc[i][j];
        }
    }
}

// ---------------------------------------------------------------------------
// Kernel 4: top-9 smallest per row (tie -> lower index). Register-resident.
__global__ void topk_kernel()
{
    const int row = blockIdx.x;            // b*N + n
    const float* d = g_dist + (size_t)row * NN;
    const int t = threadIdx.x;             // 256 threads
    const int lane = t & 31, w = t >> 5;
    float v0 = d[t], v1 = d[t+256], v2 = d[t+512], v3 = d[t+768];
    __shared__ float swv[8];
    __shared__ int   swi[8];
    __shared__ int   sbest;

    for (int kp = 0; kp < KNN; kp++) {
        // local min; index = t + j*256, strict < keeps lowest j (lowest index)
        float bv = v0; int bj = 0;
        if (v1 < bv) { bv = v1; bj = 1; }
        if (v2 < bv) { bv = v2; bj = 2; }
        if (v3 < bv) { bv = v3; bj = 3; }
        int bi = t + (bj << 8);
        // warp reduce (min value, tie -> min index)
#pragma unroll
        for (int o = 16; o; o >>= 1) {
            float ov = __shfl_down_sync(0xffffffffu, bv, o);
            int   oi = __shfl_down_sync(0xffffffffu, bi, o);
            if (ov < bv || (ov == bv && oi < bi)) { bv = ov; bi = oi; }
        }
        if (!lane) { swv[w] = bv; swi[w] = bi; }
        __syncthreads();
        if (w == 0) {
            float rv = (lane < 8) ? swv[lane] : INFINITY;
            int   ri = (lane < 8) ? swi[lane] : 0x7fffffff;
#pragma unroll
            for (int o = 4; o; o >>= 1) {
                float ov = __shfl_down_sync(0xffffffffu, rv, o);
                int   oi = __shfl_down_sync(0xffffffffu, ri, o);
                if (ov < rv || (ov == rv && oi < ri)) { rv = ov; ri = oi; }
            }
            if (!lane) { sbest = ri; g_idx[row*KNN + kp] = ri; }
        }
        __syncthreads();
        int sel = sbest;
        if      (sel == t      ) v0 = INFINITY;
        else if (sel == t + 256) v1 = INFINITY;
        else if (sel == t + 512) v2 = INFINITY;
        else if (sel == t + 768) v3 = INFINITY;
    }
}

// ---------------------------------------------------------------------------
// Kernel 5: MRConv + interleave: m[2c]=h[c], m[2c+1]=max_j(h[idx_j,c]-h[n,c])
__global__ void mrconv_kernel()
{
    const int n = blockIdx.x, b = blockIdx.y, c = threadIdx.x;  // 256 threads
    const size_t rowb = (size_t)b*NN + n;
    __shared__ int sidx[KNN];
    if (c < KNN) sidx[c] = g_idx[rowb*KNN + c];
    __syncthreads();
    float v = g_h[rowb*CC + c];
    float mx = -INFINITY;
#pragma unroll
    for (int j = 0; j < KNN; j++) {
        int nb = sidx[j];
        mx = fmaxf(mx, g_h[((size_t)b*NN + nb)*CC + c] - v);
    }
    float* mo = g_m + rowb*2*CC;
    mo[2*c]   = v;
    mo[2*c+1] = mx;
}

// ---------------------------------------------------------------------------
// Kernel 6 (tf32 mma): g = GELU(BN2(GBN(gc_w @ m + gc_b)))
__global__ void __launch_bounds__(256) gc_kernel(
    const float* __restrict__ w, const float* __restrict__ bias,
    const float* __restrict__ g1g, const float* __restrict__ g1b,
    const float* __restrict__ g1m, const float* __restrict__ g1v,
    const float* __restrict__ g2g, const float* __restrict__ g2b,
    const float* __restrict__ g2m, const float* __restrict__ g2v)
{
    __shared__ uint32_t Ask[16*SA];
    __shared__ uint32_t Bsk[16*SB];
    const int r0 = blockIdx.x * 128;
    const int c0 = blockIdx.y * 64;
    const int tid = threadIdx.x;

    float acc[2][4][4];
#pragma unroll
    for (int mi = 0; mi < 2; mi++)
#pragma unroll
        for (int ni = 0; ni < 4; ni++)
#pragma unroll
            for (int q = 0; q < 4; q++) acc[mi][ni][q] = 0.f;

    tf32_gemm_tile<2*CC>(g_m + (size_t)r0*(2*CC), w + (size_t)c0*(2*CC), Ask, Bsk, acc, tid);

    const int lane = tid & 31, wp = tid >> 5;
    const int gid = lane >> 2, tig = lane & 3;
    const int wm = (wp & 3) * 32, wn = (wp >> 2) * 32;
#pragma unroll
    for (int ni = 0; ni < 4; ni++) {
        int col = c0 + wn + ni*8 + 2*tig;
        float s1a = g1g[col]   * rsqrtf(g1v[col]   + 1e-5f);
        float s1b = g1g[col+1] * rsqrtf(g1v[col+1] + 1e-5f);
        float t1a = g1b[col]   - g1m[col]  *s1a;
        float t1b = g1b[col+1] - g1m[col+1]*s1b;
        float s2a = g2g[col]   * rsqrtf(g2v[col]   + 1e-5f);
        float s2b = g2g[col+1] * rsqrtf(g2v[col+1] + 1e-5f);
        float t2a = g2b[col]   - g2m[col]  *s2a;
        float t2b = g2b[col+1] - g2m[col+1]*s2b;
        float bia = bias[col], bib = bias[col+1];
#pragma unroll
        for (int mi = 0; mi < 2; mi++) {
            int r_lo = r0 + wm + mi*16 + gid;
#pragma unroll
            for (int h = 0; h < 2; h++) {       // h=0: rows gid, h=1: gid+8
                int r = r_lo + h*8;
                float ya = ((acc[mi][ni][2*h]   + bia)*s1a + t1a)*s2a + t2a;
                float yb = ((acc[mi][ni][2*h+1] + bib)*s1b + t1b)*s2b + t2b;
                ya = 0.5f * ya * (1.f + erff(ya * 0.70710678118654752440f));
                yb = 0.5f * yb * (1.f + erff(yb * 0.70710678118654752440f));
                float2 v2; v2.x = ya; v2.y = yb;
                *(float2*)(g_g + (size_t)r*HID + col) = v2;
            }
        }
    }
}

// ---------------------------------------------------------------------------
// Kernel 7 (tf32 mma): out = BN3(fc2_w @ g + fc2_b) + x, (B,C,N) layout via
// smem restage for coalesced transposed stores.
__global__ void __launch_bounds__(256) fc2_kernel(
    const float* __restrict__ w, const float* __restrict__ bias,
    const float* __restrict__ bg, const float* __restrict__ bbta,
    const float* __restrict__ bm, const float* __restrict__ bv,
    const float* __restrict__ x, float* __restrict__ out)
{
    __shared__ uint32_t Ask[16*SA];
    __shared__ uint32_t Bsk[16*SB];
    __shared__ float Os[128*65];
    const int r0 = blockIdx.x * 128;
    const int c0 = blockIdx.y * 64;
    const int tid = threadIdx.x;

    float acc[2][4][4];
#pragma unroll
    for (int mi = 0; mi < 2; mi++)
#pragma unroll
        for (int ni = 0; ni < 4; ni++)
#pragma unroll
            for (int q = 0; q < 4; q++) acc[mi][ni][q] = 0.f;

    tf32_gemm_tile<HID>(g_g + (size_t)r0*HID, w + (size_t)c0*HID, Ask, Bsk, acc, tid);

    const int lane = tid & 31, wp = tid >> 5;
    const int gid = lane >> 2, tig = lane & 3;
    const int wm = (wp & 3) * 32, wn = (wp >> 2) * 32;
#pragma unroll
    for (int ni = 0; ni < 4; ni++) {
        int cl = wn + ni*8 + 2*tig;
        int col = c0 + cl;
        float sca = bg[col]   * rsqrtf(bv[col]   + 1e-5f);
        float scb = bg[col+1] * rsqrtf(bv[col+1] + 1e-5f);
        float sha = bbta[col]   - bm[col]  *sca;
        float shb = bbta[col+1] - bm[col+1]*scb;
        float bia = bias[col], bib = bias[col+1];
#pragma unroll
        for (int mi = 0; mi < 2; mi++) {
            int rl_lo = wm + mi*16 + gid;
#pragma unroll
            for (int h = 0; h < 2; h++) {
                int rl = rl_lo + h*8;
                Os[rl*65 + cl]     = (acc[mi][ni][2*h]   + bia)*sca + sha;
                Os[rl*65 + cl + 1] = (acc[mi][ni][2*h+1] + bib)*scb + shb;
            }
        }
    }
    __syncthreads();
    const int b = r0 >> 10;
    const int nbase = r0 & 1023;
#pragma unroll
    for (int it = 0; it < 32; it++) {
        int e = tid + it*256;     // 8192 elements
        int nl = e & 127;
        int cl = e >> 7;
        size_t o = (size_t)b*CC*NN + (size_t)(c0 + cl)*NN + (nbase + nl);
        out[o] = Os[nl*65 + cl] + x[o];
    }
}

// ---------------------------------------------------------------------------
extern "C" void kernel_launch(void* const* d_in, const int* in_sizes, int n_in,
                              void* d_out, int out_size)
{
    const float* x     = (const float*)d_in[0];
    const float* fc1_w = (const float*)d_in[1];
    const float* fc1_b = (const float*)d_in[2];
    const float* bn1_g = (const float*)d_in[3];
    const float* bn1_b = (const float*)d_in[4];
    const float* bn1_m = (const float*)d_in[5];
    const float* bn1_v = (const float*)d_in[6];
    const float* gc_w  = (const float*)d_in[7];
    const float* gc_b  = (const float*)d_in[8];
    const float* gbn_g = (const float*)d_in[9];
    const float* gbn_b = (const float*)d_in[10];
    const float* gbn_m = (const float*)d_in[11];
    const float* gbn_v = (const float*)d_in[12];
    const float* bn2_g = (const float*)d_in[13];
    const float* bn2_b = (const float*)d_in[14];
    const float* bn2_m = (const float*)d_in[15];
    const float* bn2_v = (const float*)d_in[16];
    const float* fc2_w = (const float*)d_in[17];
    const float* fc2_b = (const float*)d_in[18];
    const float* bn3_g = (const float*)d_in[19];
    const float* bn3_b = (const float*)d_in[20];
    const float* bn3_m = (const float*)d_in[21];
    const float* bn3_v = (const float*)d_in[22];
    float* out = (float*)d_out;

    // 1) fc1 + BN1 -> h (node-major), exact fp32 (protects kNN ranking)
    {
        dim3 grid(NN/Bb, CC/Bn, BB);
        fc1_kernel<<<grid, 256>>>(x, fc1_w, fc1_b, bn1_g, bn1_b, bn1_m, bn1_v);
    }
    // 2) row norms
    x2_kernel<<<(MTOT*32)/256, 256>>>();
    // 3) pairwise distances, exact fp32
    {
        dim3 grid(NN/Bb, NN/Bn, BB);
        dist_kernel<<<grid, 256>>>();
    }
    // 4) top-9 nearest per node
    topk_kernel<<<MTOT, 256>>>();
    // 5) MRConv + interleave
    {
        dim3 grid(NN, BB);
        mrconv_kernel<<<grid, 256>>>();
    }
    // 6) gc + gbn + bn2 + GELU (tf32 tensor cores)
    {
        dim3 grid(MTOT/128, HID/64);
        gc_kernel<<<grid, 256>>>(gc_w, gc_b, gbn_g, gbn_b, gbn_m, gbn_v,
                                 bn2_g, bn2_b, bn2_m, bn2_v);
    }
    // 7) fc2 + bn3 + residual (tf32 tensor cores)
    {
        dim3 grid(MTOT/128, CC/64);
        fc2_kernel<<<grid, 256>>>(fc2_w, fc2_b, bn3_g, bn3_b, bn3_m, bn3_v, x, out);
    }
}

// round 5
// speedup vs baseline: 1.7392x; 1.1288x over previous
#include <cuda_runtime.h>
#include <cuda_bf16.h>
#include <stdint.h>
#include <math.h>

// Problem constants
#define BB   16
#define CC   256
#define NN   1024
#define HID  512
#define KNN  9
#define MTOT (BB*NN)   // 16384

// FFMA GEMM tiling (fc1, dist)
#define Bb 64
#define Bn 64
#define KT 16

// tf32 GEMM smem strides (words); both ≡ 4 (mod 32) for conflict-free frag loads
#define SA 132   // 128 + 4
#define SB 68    // 64 + 4

// ---------------- scratch (static device globals; no allocations) ----------
__device__ float g_h   [(size_t)BB*NN*CC];      // node-major h: [(b*N+n)*C + c]
__device__ float g_x2  [BB*NN];                 // row squared norms
__device__ float g_dist[(size_t)BB*NN*NN];      // per-batch distance matrices
__device__ int   g_idx [BB*NN*KNN];             // knn indices (batch-local)
__device__ float g_m   [(size_t)BB*NN*2*CC];    // interleaved [h, maxdiff]
__device__ float g_g   [(size_t)BB*NN*HID];     // post-GELU activations

// ---------------------------------------------------------------------------
// tf32 helpers
__device__ __forceinline__ uint32_t f2tf32(float f){
    uint32_t u; asm("cvt.rna.tf32.f32 %0, %1;" : "=r"(u) : "f"(f)); return u;
}
__device__ __forceinline__ void mma_tf32(float* c,
    uint32_t a0, uint32_t a1, uint32_t a2, uint32_t a3, uint32_t b0, uint32_t b1)
{
    asm volatile("mma.sync.aligned.m16n8k8.row.col.f32.tf32.tf32.f32 "
        "{%0,%1,%2,%3}, {%4,%5,%6,%7}, {%8,%9}, {%0,%1,%2,%3};"
        : "+f"(c[0]), "+f"(c[1]), "+f"(c[2]), "+f"(c[3])
        : "r"(a0), "r"(a1), "r"(a2), "r"(a3), "r"(b0), "r"(b1));
}

// tf32 GEMM core: block tile 128x64, 256 threads (8 warps, warp tile 32x32).
template<int K>
__device__ __forceinline__ void tf32_gemm_tile(
    const float* __restrict__ A, const float* __restrict__ B,
    uint32_t* Ask, uint32_t* Bsk, float acc[2][4][4], int tid)
{
    const int lane = tid & 31, w = tid >> 5;
    const int gid = lane >> 2, tig = lane & 3;
    const int wm = (w & 3) * 32, wn = (w >> 2) * 32;
    const int am = tid >> 1, ak = (tid & 1) * 8;   // A loader: row, k-offset
    const int bn = tid >> 2, bk = (tid & 3) * 4;   // B loader

    for (int k0 = 0; k0 < K; k0 += 16) {
        float4 a4a = *(const float4*)(A + (size_t)am*K + k0 + ak);
        float4 a4b = *(const float4*)(A + (size_t)am*K + k0 + ak + 4);
        Ask[(ak+0)*SA + am] = f2tf32(a4a.x);
        Ask[(ak+1)*SA + am] = f2tf32(a4a.y);
        Ask[(ak+2)*SA + am] = f2tf32(a4a.z);
        Ask[(ak+3)*SA + am] = f2tf32(a4a.w);
        Ask[(ak+4)*SA + am] = f2tf32(a4b.x);
        Ask[(ak+5)*SA + am] = f2tf32(a4b.y);
        Ask[(ak+6)*SA + am] = f2tf32(a4b.z);
        Ask[(ak+7)*SA + am] = f2tf32(a4b.w);
        float4 b4 = *(const float4*)(B + (size_t)bn*K + k0 + bk);
        Bsk[(bk+0)*SB + bn] = f2tf32(b4.x);
        Bsk[(bk+1)*SB + bn] = f2tf32(b4.y);
        Bsk[(bk+2)*SB + bn] = f2tf32(b4.z);
        Bsk[(bk+3)*SB + bn] = f2tf32(b4.w);
        __syncthreads();
#pragma unroll
        for (int ks = 0; ks < 16; ks += 8) {
            uint32_t af[2][4], bf[4][2];
#pragma unroll
            for (int mi = 0; mi < 2; mi++) {
                int mo = wm + mi*16 + gid;
                af[mi][0] = Ask[(ks+tig  )*SA + mo];
                af[mi][1] = Ask[(ks+tig  )*SA + mo + 8];
                af[mi][2] = Ask[(ks+tig+4)*SA + mo];
                af[mi][3] = Ask[(ks+tig+4)*SA + mo + 8];
            }
#pragma unroll
            for (int ni = 0; ni < 4; ni++) {
                int no = wn + ni*8 + gid;
                bf[ni][0] = Bsk[(ks+tig  )*SB + no];
                bf[ni][1] = Bsk[(ks+tig+4)*SB + no];
            }
#pragma unroll
            for (int mi = 0; mi < 2; mi++)
#pragma unroll
                for (int ni = 0; ni < 4; ni++)
                    mma_tf32(acc[mi][ni], af[mi][0], af[mi][1], af[mi][2], af[mi][3],
                             bf[ni][0], bf[ni][1]);
        }
        __syncthreads();
    }
}

// ---------------------------------------------------------------------------
// Kernel 1 (FFMA, exact): h = BN1(fc1_w @ x + fc1_b), node-major output.
__global__ void fc1_kernel(const float* __restrict__ x,
                           const float* __restrict__ w,
                           const float* __restrict__ bias,
                           const float* __restrict__ bg, const float* __restrict__ bbta,
                           const float* __restrict__ bm, const float* __restrict__ bv)
{
    __shared__ float As[KT][Bb+4];
    __shared__ float Ws[KT][Bn+4];
    const int b  = blockIdx.z;
    const int n0 = blockIdx.x * Bb;
    const int c0 = blockIdx.y * Bn;
    const int tid = threadIdx.x;
    const int tx = tid & 15, ty = tid >> 4;
    const float* xb = x + (size_t)b*CC*NN;

    float acc[4][4];
#pragma unroll
    for (int i = 0; i < 4; i++)
#pragma unroll
        for (int j = 0; j < 4; j++) acc[i][j] = 0.f;

    for (int k0 = 0; k0 < CC; k0 += KT) {
#pragma unroll
        for (int i = 0; i < 4; i++) {
            int e = tid + i*256;
            int mm = e & 63, kk = e >> 6;
            As[kk][mm] = xb[(size_t)(k0+kk)*NN + n0 + mm];
        }
#pragma unroll
        for (int i = 0; i < 4; i++) {
            int e = tid + i*256;
            int kk = e & 15, nn = e >> 4;
            Ws[kk][nn] = w[(size_t)(c0+nn)*CC + k0 + kk];
        }
        __syncthreads();
#pragma unroll
        for (int kk = 0; kk < KT; kk++) {
            float a[4], wv[4];
#pragma unroll
            for (int i = 0; i < 4; i++) a[i]  = As[kk][ty*4+i];
#pragma unroll
            for (int j = 0; j < 4; j++) wv[j] = Ws[kk][tx*4+j];
#pragma unroll
            for (int i = 0; i < 4; i++)
#pragma unroll
                for (int j = 0; j < 4; j++) acc[i][j] = fmaf(a[i], wv[j], acc[i][j]);
        }
        __syncthreads();
    }
#pragma unroll
    for (int j = 0; j < 4; j++) {
        int c = c0 + tx*4 + j;
        float sc = bg[c] * rsqrtf(bv[c] + 1e-5f);
        float sh = bbta[c] - bm[c]*sc;
        float bi = bias[c];
#pragma unroll
        for (int i = 0; i < 4; i++) {
            int n = n0 + ty*4 + i;
            g_h[((size_t)b*NN + n)*CC + c] = (acc[i][j] + bi)*sc + sh;
        }
    }
}

// ---------------------------------------------------------------------------
// Kernel 2: row squared norms of h.
__global__ void x2_kernel()
{
    int warp = (blockIdx.x*blockDim.x + threadIdx.x) >> 5;
    int lane = threadIdx.x & 31;
    if (warp >= MTOT) return;
    const float* r = g_h + (size_t)warp*CC;
    float s = 0.f;
    for (int c = lane; c < CC; c += 32) { float v = r[c]; s = fmaf(v, v, s); }
#pragma unroll
    for (int o = 16; o; o >>= 1) s += __shfl_xor_sync(0xffffffffu, s, o);
    if (!lane) g_x2[warp] = s;
}

// ---------------------------------------------------------------------------
// Kernel 3 (FFMA, exact, symmetric): dist[b][n][m] = x2[n]+x2[m]-2<h_n,h_m>.
// Only upper-triangular block pairs computed; transpose tile written via smem
// restage. FMA order identical to the full version -> bit-identical output.
__global__ void dist_kernel()
{
    __shared__ float As[KT][Bb+4];
    __shared__ float Ws[KT][Bn+4];
    __shared__ float Os[64][65];
    const int b = blockIdx.z;
    // unrank triangular pair index -> (bi, bj), bi <= bj
    int t4 = blockIdx.x;
    int bi = 0;
    while (t4 >= (NN/Bb) - bi) { t4 -= (NN/Bb) - bi; bi++; }
    const int bj = bi + t4;
    const int n0 = bi * Bb;
    const int m0 = bj * Bn;
    const int tid = threadIdx.x;
    const int tx = tid & 15, ty = tid >> 4;
    const float* hb = g_h + (size_t)b*NN*CC;

    float acc[4][4];
#pragma unroll
    for (int i = 0; i < 4; i++)
#pragma unroll
        for (int j = 0; j < 4; j++) acc[i][j] = 0.f;

    for (int k0 = 0; k0 < CC; k0 += KT) {
#pragma unroll
        for (int i = 0; i < 4; i++) {
            int e = tid + i*256;
            int kk = e & 15, mm = e >> 4;
            As[kk][mm] = hb[(size_t)(n0+mm)*CC + k0 + kk];
        }
#pragma unroll
        for (int i = 0; i < 4; i++) {
            int e = tid + i*256;
            int kk = e & 15, nn = e >> 4;
            Ws[kk][nn] = hb[(size_t)(m0+nn)*CC + k0 + kk];
        }
        __syncthreads();
#pragma unroll
        for (int kk = 0; kk < KT; kk++) {
            float a[4], wv[4];
#pragma unroll
            for (int i = 0; i < 4; i++) a[i]  = As[kk][ty*4+i];
#pragma unroll
            for (int j = 0; j < 4; j++) wv[j] = Ws[kk][tx*4+j];
#pragma unroll
            for (int i = 0; i < 4; i++)
#pragma unroll
                for (int j = 0; j < 4; j++) acc[i][j] = fmaf(a[i], wv[j], acc[i][j]);
        }
        __syncthreads();
    }
    float* db = g_dist + (size_t)b*NN*NN;
    float xm[4];
#pragma unroll
    for (int j = 0; j < 4; j++) xm[j] = g_x2[b*NN + m0 + tx*4 + j];
#pragma unroll
    for (int i = 0; i < 4; i++) {
        int n = n0 + ty*4 + i;
        float xn = g_x2[b*NN + n];
#pragma unroll
        for (int j = 0; j < 4; j++) {
            float v = xn + xm[j] - 2.f*acc[i][j];
            db[(size_t)n*NN + m0 + tx*4 + j] = v;     // direct tile
            Os[tx*4 + j][ty*4 + i] = v;               // transpose stage
        }
    }
    __syncthreads();
    // write transpose tile: dist[m][n] (coalesced over n)
#pragma unroll
    for (int it = 0; it < 16; it++) {
        int e = tid + it*256;
        int il = e & 63;          // local n (fastest)
        int jl = e >> 6;          // local m
        db[(size_t)(m0 + jl)*NN + n0 + il] = Os[jl][il];
    }
}

// ---------------------------------------------------------------------------
// Kernel 4: top-9 smallest per row (tie -> lower index).
// Packed u64 keys (monotonic float || index); per-thread local min cached and
// only recomputed by the owner of the extracted element.
__global__ void topk_kernel()
{
    const int row = blockIdx.x;            // b*N + n
    const float* d = g_dist + (size_t)row * NN;
    const int t = threadIdx.x;             // 256 threads
    const int lane = t & 31, w = t >> 5;

    unsigned long long k[4];
#pragma unroll
    for (int j = 0; j < 4; j++) {
        float v = d[t + j*256];
        unsigned u = __float_as_uint(v);
        u = (u & 0x80000000u) ? ~u : (u | 0x80000000u);   // monotonic map
        k[j] = ((unsigned long long)u << 32) | (unsigned)(t + j*256);
    }
    unsigned long long lm = min(min(k[0], k[1]), min(k[2], k[3]));

    __shared__ unsigned long long swk[8];
    __shared__ unsigned long long sbest;

    for (int kp = 0; kp < KNN; kp++) {
        unsigned long long bkey = lm;
#pragma unroll
        for (int o = 16; o; o >>= 1) {
            unsigned long long ob = __shfl_down_sync(0xffffffffu, bkey, o);
            bkey = min(bkey, ob);
        }
        if (!lane) swk[w] = bkey;
        __syncthreads();
        if (w == 0) {
            unsigned long long rb = (lane < 8) ? swk[lane] : ~0ull;
#pragma unroll
            for (int o = 4; o; o >>= 1) {
                unsigned long long ob = __shfl_down_sync(0xffffffffu, rb, o);
                rb = min(rb, ob);
            }
            if (!lane) {
                sbest = rb;
                g_idx[row*KNN + kp] = (int)(rb & 0xffffffffu);
            }
        }
        __syncthreads();
        unsigned long long sel = sbest;
        int sidx = (int)(sel & 0xffffffffu);
        if ((sidx & 255) == t) {           // owner recomputes its cached min
            int jj = sidx >> 8;
            k[jj] = ~0ull;
            lm = min(min(k[0], k[1]), min(k[2], k[3]));
        }
    }
}

// ---------------------------------------------------------------------------
// Kernel 5: MRConv + interleave: m[2c]=h[c], m[2c+1]=max_j(h[idx_j,c]-h[n,c])
__global__ void mrconv_kernel()
{
    const int n = blockIdx.x, b = blockIdx.y, c = threadIdx.x;  // 256 threads
    const size_t rowb = (size_t)b*NN + n;
    __shared__ int sidx[KNN];
    if (c < KNN) sidx[c] = g_idx[rowb*KNN + c];
    __syncthreads();
    float v = g_h[rowb*CC + c];
    float mx = -INFINITY;
#pragma unroll
    for (int j = 0; j < KNN; j++) {
        int nb = sidx[j];
        mx = fmaxf(mx, g_h[((size_t)b*NN + nb)*CC + c] - v);
    }
    float* mo = g_m + rowb*2*CC;
    mo[2*c]   = v;
    mo[2*c+1] = mx;
}

// ---------------------------------------------------------------------------
// Kernel 6 (tf32 mma): g = GELU(BN2(GBN(gc_w @ m + gc_b)))
__global__ void __launch_bounds__(256) gc_kernel(
    const float* __restrict__ w, const float* __restrict__ bias,
    const float* __restrict__ g1g, const float* __restrict__ g1b,
    const float* __restrict__ g1m, const float* __restrict__ g1v,
    const float* __restrict__ g2g, const float* __restrict__ g2b,
    const float* __restrict__ g2m, const float* __restrict__ g2v)
{
    __shared__ uint32_t Ask[16*SA];
    __shared__ uint32_t Bsk[16*SB];
    const int r0 = blockIdx.x * 128;
    const int c0 = blockIdx.y * 64;
    const int tid = threadIdx.x;

    float acc[2][4][4];
#pragma unroll
    for (int mi = 0; mi < 2; mi++)
#pragma unroll
        for (int ni = 0; ni < 4; ni++)
#pragma unroll
            for (int q = 0; q < 4; q++) acc[mi][ni][q] = 0.f;

    tf32_gemm_tile<2*CC>(g_m + (size_t)r0*(2*CC), w + (size_t)c0*(2*CC), Ask, Bsk, acc, tid);

    const int lane = tid & 31, wp = tid >> 5;
    const int gid = lane >> 2, tig = lane & 3;
    const int wm = (wp & 3) * 32, wn = (wp >> 2) * 32;
#pragma unroll
    for (int ni = 0; ni < 4; ni++) {
        int col = c0 + wn + ni*8 + 2*tig;
        float s1a = g1g[col]   * rsqrtf(g1v[col]   + 1e-5f);
        float s1b = g1g[col+1] * rsqrtf(g1v[col+1] + 1e-5f);
        float t1a = g1b[col]   - g1m[col]  *s1a;
        float t1b = g1b[col+1] - g1m[col+1]*s1b;
        float s2a = g2g[col]   * rsqrtf(g2v[col]   + 1e-5f);
        float s2b = g2g[col+1] * rsqrtf(g2v[col+1] + 1e-5f);
        float t2a = g2b[col]   - g2m[col]  *s2a;
        float t2b = g2b[col+1] - g2m[col+1]*s2b;
        float bia = bias[col], bib = bias[col+1];
#pragma unroll
        for (int mi = 0; mi < 2; mi++) {
            int r_lo = r0 + wm + mi*16 + gid;
#pragma unroll
            for (int h = 0; h < 2; h++) {       // h=0: rows gid, h=1: gid+8
                int r = r_lo + h*8;
                float ya = ((acc[mi][ni][2*h]   + bia)*s1a + t1a)*s2a + t2a;
                float yb = ((acc[mi][ni][2*h+1] + bib)*s1b + t1b)*s2b + t2b;
                ya = 0.5f * ya * (1.f + erff(ya * 0.70710678118654752440f));
                yb = 0.5f * yb * (1.f + erff(yb * 0.70710678118654752440f));
                float2 v2; v2.x = ya; v2.y = yb;
                *(float2*)(g_g + (size_t)r*HID + col) = v2;
            }
        }
    }
}

// ---------------------------------------------------------------------------
// Kernel 7 (tf32 mma): out = BN3(fc2_w @ g + fc2_b) + x, (B,C,N) layout via
// smem restage for coalesced transposed stores.
__global__ void __launch_bounds__(256) fc2_kernel(
    const float* __restrict__ w, const float* __restrict__ bias,
    const float* __restrict__ bg, const float* __restrict__ bbta,
    const float* __restrict__ bm, const float* __restrict__ bv,
    const float* __restrict__ x, float* __restrict__ out)
{
    __shared__ uint32_t Ask[16*SA];
    __shared__ uint32_t Bsk[16*SB];
    __shared__ float Os[128*65];
    const int r0 = blockIdx.x * 128;
    const int c0 = blockIdx.y * 64;
    const int tid = threadIdx.x;

    float acc[2][4][4];
#pragma unroll
    for (int mi = 0; mi < 2; mi++)
#pragma unroll
        for (int ni = 0; ni < 4; ni++)
#pragma unroll
            for (int q = 0; q < 4; q++) acc[mi][ni][q] = 0.f;

    tf32_gemm_tile<HID>(g_g + (size_t)r0*HID, w + (size_t)c0*HID, Ask, Bsk, acc, tid);

    const int lane = tid & 31, wp = tid >> 5;
    const int gid = lane >> 2, tig = lane & 3;
    const int wm = (wp & 3) * 32, wn = (wp >> 2) * 32;
#pragma unroll
    for (int ni = 0; ni < 4; ni++) {
        int cl = wn + ni*8 + 2*tig;
        int col = c0 + cl;
        float sca = bg[col]   * rsqrtf(bv[col]   + 1e-5f);
        float scb = bg[col+1] * rsqrtf(bv[col+1] + 1e-5f);
        float sha = bbta[col]   - bm[col]  *sca;
        float shb = bbta[col+1] - bm[col+1]*scb;
        float bia = bias[col], bib = bias[col+1];
#pragma unroll
        for (int mi = 0; mi < 2; mi++) {
            int rl_lo = wm + mi*16 + gid;
#pragma unroll
            for (int h = 0; h < 2; h++) {
                int rl = rl_lo + h*8;
                Os[rl*65 + cl]     = (acc[mi][ni][2*h]   + bia)*sca + sha;
                Os[rl*65 + cl + 1] = (acc[mi][ni][2*h+1] + bib)*scb + shb;
            }
        }
    }
    __syncthreads();
    const int b = r0 >> 10;
    const int nbase = r0 & 1023;
#pragma unroll
    for (int it = 0; it < 32; it++) {
        int e = tid + it*256;     // 8192 elements
        int nl = e & 127;
        int cl = e >> 7;
        size_t o = (size_t)b*CC*NN + (size_t)(c0 + cl)*NN + (nbase + nl);
        out[o] = Os[nl*65 + cl] + x[o];
    }
}

// ---------------------------------------------------------------------------
extern "C" void kernel_launch(void* const* d_in, const int* in_sizes, int n_in,
                              void* d_out, int out_size)
{
    const float* x     = (const float*)d_in[0];
    const float* fc1_w = (const float*)d_in[1];
    const float* fc1_b = (const float*)d_in[2];
    const float* bn1_g = (const float*)d_in[3];
    const float* bn1_b = (const float*)d_in[4];
    const float* bn1_m = (const float*)d_in[5];
    const float* bn1_v = (const float*)d_in[6];
    const float* gc_w  = (const float*)d_in[7];
    const float* gc_b  = (const float*)d_in[8];
    const float* gbn_g = (const float*)d_in[9];
    const float* gbn_b = (const float*)d_in[10];
    const float* gbn_m = (const float*)d_in[11];
    const float* gbn_v = (const float*)d_in[12];
    const float* bn2_g = (const float*)d_in[13];
    const float* bn2_b = (const float*)d_in[14];
    const float* bn2_m = (const float*)d_in[15];
    const float* bn2_v = (const float*)d_in[16];
    const float* fc2_w = (const float*)d_in[17];
    const float* fc2_b = (const float*)d_in[18];
    const float* bn3_g = (const float*)d_in[19];
    const float* bn3_b = (const float*)d_in[20];
    const float* bn3_m = (const float*)d_in[21];
    const float* bn3_v = (const float*)d_in[22];
    float* out = (float*)d_out;

    // 1) fc1 + BN1 -> h (node-major), exact fp32 (protects kNN ranking)
    {
        dim3 grid(NN/Bb, CC/Bn, BB);
        fc1_kernel<<<grid, 256>>>(x, fc1_w, fc1_b, bn1_g, bn1_b, bn1_m, bn1_v);
    }
    // 2) row norms
    x2_kernel<<<(MTOT*32)/256, 256>>>();
    // 3) pairwise distances, exact fp32, symmetric (triangular blocks)
    {
        const int nb = NN/Bb;                     // 16
        dim3 grid(nb*(nb+1)/2, 1, BB);            // 136 x 1 x 16
        dist_kernel<<<grid, 256>>>();
    }
    // 4) top-9 nearest per node
    topk_kernel<<<MTOT, 256>>>();
    // 5) MRConv + interleave
    {
        dim3 grid(NN, BB);
        mrconv_kernel<<<grid, 256>>>();
    }
    // 6) gc + gbn + bn2 + GELU (tf32 tensor cores)
    {
        dim3 grid(MTOT/128, HID/64);
        gc_kernel<<<grid, 256>>>(gc_w, gc_b, gbn_g, gbn_b, gbn_m, gbn_v,
                                 bn2_g, bn2_b, bn2_m, bn2_v);
    }
    // 7) fc2 + bn3 + residual (tf32 tensor cores)
    {
        dim3 grid(MTOT/128, CC/64);
        fc2_kernel<<<grid, 256>>>(fc2_w, fc2_b, bn3_g, bn3_b, bn3_m, bn3_v, x, out);
    }
}

// round 6
// speedup vs baseline: 2.5293x; 1.4543x over previous
#include <cuda_runtime.h>
#include <cuda_bf16.h>
#include <stdint.h>
#include <math.h>

// Problem constants
#define BB   16
#define CC   256
#define NN   1024
#define HID  512
#define KNN  9
#define MTOT (BB*NN)   // 16384

// smem strides (u32 words). SA%32==8 -> A-frag LDS conflict-free (tig*8+gid),
// SB%32==8 -> B-frag LDS conflict-free.
#define SA 136
#define SB 72

// ---------------- scratch (static device globals; no allocations) ----------
__device__ float g_xt  [(size_t)MTOT*CC];       // x transposed to node-major
__device__ float g_h   [(size_t)MTOT*CC];       // node-major h
__device__ float g_x2  [MTOT];                  // row squared norms
__device__ float g_dist[(size_t)BB*NN*NN];      // per-batch distance matrices
__device__ int   g_idx [MTOT*KNN];              // knn indices (batch-local)
__device__ float g_m   [(size_t)MTOT*2*CC];     // interleaved [h, maxdiff]
__device__ float g_g   [(size_t)MTOT*HID];      // post-GELU activations

// ---------------------------------------------------------------------------
// mma helpers
__device__ __forceinline__ uint32_t f2tf32(float f){
    uint32_t u; asm("cvt.rna.tf32.f32 %0, %1;" : "=r"(u) : "f"(f)); return u;
}
__device__ __forceinline__ void mma_tf32(float* c,
    uint32_t a0, uint32_t a1, uint32_t a2, uint32_t a3, uint32_t b0, uint32_t b1)
{
    asm volatile("mma.sync.aligned.m16n8k8.row.col.f32.tf32.tf32.f32 "
        "{%0,%1,%2,%3}, {%4,%5,%6,%7}, {%8,%9}, {%0,%1,%2,%3};"
        : "+f"(c[0]), "+f"(c[1]), "+f"(c[2]), "+f"(c[3])
        : "r"(a0), "r"(a1), "r"(a2), "r"(a3), "r"(b0), "r"(b1));
}
__device__ __forceinline__ void mma_bf16(float* c,
    uint32_t a0, uint32_t a1, uint32_t a2, uint32_t a3, uint32_t b0, uint32_t b1)
{
    asm volatile("mma.sync.aligned.m16n8k16.row.col.f32.bf16.bf16.f32 "
        "{%0,%1,%2,%3}, {%4,%5,%6,%7}, {%8,%9}, {%0,%1,%2,%3};"
        : "+f"(c[0]), "+f"(c[1]), "+f"(c[2]), "+f"(c[3])
        : "r"(a0), "r"(a1), "r"(a2), "r"(a3), "r"(b0), "r"(b1));
}

// split two floats (consecutive k) into packed bf16x2 hi and lo words
__device__ __forceinline__ void splitpack(float x, float y, uint32_t& h, uint32_t& l){
    __nv_bfloat16 hx = __float2bfloat16(x);
    __nv_bfloat16 hy = __float2bfloat16(y);
    float rx = x - __bfloat162float(hx);
    float ry = y - __bfloat162float(hy);
    __nv_bfloat16 lx = __float2bfloat16(rx);
    __nv_bfloat16 ly = __float2bfloat16(ry);
    uint16_t hxb = *(uint16_t*)&hx, hyb = *(uint16_t*)&hy;
    uint16_t lxb = *(uint16_t*)&lx, lyb = *(uint16_t*)&ly;
    h = ((uint32_t)hyb << 16) | hxb;
    l = ((uint32_t)lyb << 16) | lxb;
}

// ---------------------------------------------------------------------------
// Split-bf16 (hi+lo, 3-pass) GEMM core: block tile 128x64, 256 threads,
// 8 warps x (32x32). A row-major MxK float, B row-major NxK float, K%16==0.
// acc = A@B^T in ~fp32 accuracy (error ~2^-16 relative).
template<int K>
__device__ __forceinline__ void bfs_gemm_tile(
    const float* __restrict__ A, const float* __restrict__ B,
    uint32_t* Ah, uint32_t* Al, uint32_t* Bh, uint32_t* Bl,
    float acc[2][4][4], int tid)
{
    const int lane = tid & 31, w = tid >> 5;
    const int gid = lane >> 2, tig = lane & 3;
    const int wm = (w & 3) * 32, wn = (w >> 2) * 32;
    const int am = tid >> 1, ak2 = (tid & 1) * 4;  // A: 128 rows, 2 thr/row, 4 k2 each
    const int bn = tid >> 2, bk2 = (tid & 3) * 2;  // B: 64 rows, 4 thr/row, 2 k2 each

    for (int k0 = 0; k0 < K; k0 += 16) {
        float4 a4a = *(const float4*)(A + (size_t)am*K + k0 + ak2*2);
        float4 a4b = *(const float4*)(A + (size_t)am*K + k0 + ak2*2 + 4);
        uint32_t h0,l0,h1,l1,h2,l2,h3,l3;
        splitpack(a4a.x, a4a.y, h0, l0);
        splitpack(a4a.z, a4a.w, h1, l1);
        splitpack(a4b.x, a4b.y, h2, l2);
        splitpack(a4b.z, a4b.w, h3, l3);
        Ah[(ak2+0)*SA + am] = h0; Al[(ak2+0)*SA + am] = l0;
        Ah[(ak2+1)*SA + am] = h1; Al[(ak2+1)*SA + am] = l1;
        Ah[(ak2+2)*SA + am] = h2; Al[(ak2+2)*SA + am] = l2;
        Ah[(ak2+3)*SA + am] = h3; Al[(ak2+3)*SA + am] = l3;
        float4 b4 = *(const float4*)(B + (size_t)bn*K + k0 + bk2*2);
        uint32_t bh0,bl0,bh1,bl1;
        splitpack(b4.x, b4.y, bh0, bl0);
        splitpack(b4.z, b4.w, bh1, bl1);
        Bh[(bk2+0)*SB + bn] = bh0; Bl[(bk2+0)*SB + bn] = bl0;
        Bh[(bk2+1)*SB + bn] = bh1; Bl[(bk2+1)*SB + bn] = bl1;
        __syncthreads();
        uint32_t ahf[2][4], alf[2][4], bhf[4][2], blf[4][2];
#pragma unroll
        for (int mi = 0; mi < 2; mi++) {
            int mo = wm + mi*16 + gid;
            ahf[mi][0] = Ah[ tig   *SA + mo];
            ahf[mi][1] = Ah[ tig   *SA + mo + 8];
            ahf[mi][2] = Ah[(tig+4)*SA + mo];
            ahf[mi][3] = Ah[(tig+4)*SA + mo + 8];
            alf[mi][0] = Al[ tig   *SA + mo];
            alf[mi][1] = Al[ tig   *SA + mo + 8];
            alf[mi][2] = Al[(tig+4)*SA + mo];
            alf[mi][3] = Al[(tig+4)*SA + mo + 8];
        }
#pragma unroll
        for (int ni = 0; ni < 4; ni++) {
            int no = wn + ni*8 + gid;
            bhf[ni][0] = Bh[ tig   *SB + no];
            bhf[ni][1] = Bh[(tig+4)*SB + no];
            blf[ni][0] = Bl[ tig   *SB + no];
            blf[ni][1] = Bl[(tig+4)*SB + no];
        }
#pragma unroll
        for (int mi = 0; mi < 2; mi++)
#pragma unroll
            for (int ni = 0; ni < 4; ni++) {
                mma_bf16(acc[mi][ni], ahf[mi][0], ahf[mi][1], ahf[mi][2], ahf[mi][3],
                         bhf[ni][0], bhf[ni][1]);
                mma_bf16(acc[mi][ni], ahf[mi][0], ahf[mi][1], ahf[mi][2], ahf[mi][3],
                         blf[ni][0], blf[ni][1]);
                mma_bf16(acc[mi][ni], alf[mi][0], alf[mi][1], alf[mi][2], alf[mi][3],
                         bhf[ni][0], bhf[ni][1]);
            }
        __syncthreads();
    }
}

// ---------------------------------------------------------------------------
// tf32 single-pass GEMM core (gc, fc2): block tile 128x64, 256 threads.
template<int K>
__device__ __forceinline__ void tf32_gemm_tile(
    const float* __restrict__ A, const float* __restrict__ B,
    uint32_t* Ask, uint32_t* Bsk, float acc[2][4][4], int tid)
{
    const int lane = tid & 31, w = tid >> 5;
    const int gid = lane >> 2, tig = lane & 3;
    const int wm = (w & 3) * 32, wn = (w >> 2) * 32;
    const int am = tid >> 1, ak = (tid & 1) * 8;
    const int bn = tid >> 2, bk = (tid & 3) * 4;

    for (int k0 = 0; k0 < K; k0 += 16) {
        float4 a4a = *(const float4*)(A + (size_t)am*K + k0 + ak);
        float4 a4b = *(const float4*)(A + (size_t)am*K + k0 + ak + 4);
        Ask[(ak+0)*SA + am] = f2tf32(a4a.x);
        Ask[(ak+1)*SA + am] = f2tf32(a4a.y);
        Ask[(ak+2)*SA + am] = f2tf32(a4a.z);
        Ask[(ak+3)*SA + am] = f2tf32(a4a.w);
        Ask[(ak+4)*SA + am] = f2tf32(a4b.x);
        Ask[(ak+5)*SA + am] = f2tf32(a4b.y);
        Ask[(ak+6)*SA + am] = f2tf32(a4b.z);
        Ask[(ak+7)*SA + am] = f2tf32(a4b.w);
        float4 b4 = *(const float4*)(B + (size_t)bn*K + k0 + bk);
        Bsk[(bk+0)*SB + bn] = f2tf32(b4.x);
        Bsk[(bk+1)*SB + bn] = f2tf32(b4.y);
        Bsk[(bk+2)*SB + bn] = f2tf32(b4.z);
        Bsk[(bk+3)*SB + bn] = f2tf32(b4.w);
        __syncthreads();
#pragma unroll
        for (int ks = 0; ks < 16; ks += 8) {
            uint32_t af[2][4], bf[4][2];
#pragma unroll
            for (int mi = 0; mi < 2; mi++) {
                int mo = wm + mi*16 + gid;
                af[mi][0] = Ask[(ks+tig  )*SA + mo];
                af[mi][1] = Ask[(ks+tig  )*SA + mo + 8];
                af[mi][2] = Ask[(ks+tig+4)*SA + mo];
                af[mi][3] = Ask[(ks+tig+4)*SA + mo + 8];
            }
#pragma unroll
            for (int ni = 0; ni < 4; ni++) {
                int no = wn + ni*8 + gid;
                bf[ni][0] = Bsk[(ks+tig  )*SB + no];
                bf[ni][1] = Bsk[(ks+tig+4)*SB + no];
            }
#pragma unroll
            for (int mi = 0; mi < 2; mi++)
#pragma unroll
                for (int ni = 0; ni < 4; ni++)
                    mma_tf32(acc[mi][ni], af[mi][0], af[mi][1], af[mi][2], af[mi][3],
                             bf[ni][0], bf[ni][1]);
        }
        __syncthreads();
    }
}

// ---------------------------------------------------------------------------
// Kernel 0: transpose x (B,C,N) -> g_xt node-major [(b*N+n)*C + c]
__global__ void xt_kernel(const float* __restrict__ x)
{
    __shared__ float t[32][33];
    const int b = blockIdx.z;
    const int n0 = blockIdx.x*32, c0 = blockIdx.y*32;
    const int tx = threadIdx.x, ty = threadIdx.y;   // 32 x 8
    const float* xb = x + (size_t)b*CC*NN;
#pragma unroll
    for (int i = 0; i < 4; i++)
        t[ty+8*i][tx] = xb[(size_t)(c0+ty+8*i)*NN + n0+tx];
    __syncthreads();
#pragma unroll
    for (int i = 0; i < 4; i++)
        g_xt[(size_t)(b*NN + n0 + ty+8*i)*CC + c0 + tx] = t[tx][ty+8*i];
}

// ---------------------------------------------------------------------------
// Kernel 1 (split-bf16): h = BN1(fc1_w @ xT + fc1_b), node-major output.
__global__ void __launch_bounds__(256) fc1_kernel(
    const float* __restrict__ w, const float* __restrict__ bias,
    const float* __restrict__ bg, const float* __restrict__ bbta,
    const float* __restrict__ bm, const float* __restrict__ bv)
{
    __shared__ uint32_t Ah[8*SA], Al[8*SA], Bh[8*SB], Bl[8*SB];
    const int r0 = blockIdx.x * 128;
    const int c0 = blockIdx.y * 64;
    const int tid = threadIdx.x;

    float acc[2][4][4];
#pragma unroll
    for (int mi = 0; mi < 2; mi++)
#pragma unroll
        for (int ni = 0; ni < 4; ni++)
#pragma unroll
            for (int q = 0; q < 4; q++) acc[mi][ni][q] = 0.f;

    bfs_gemm_tile<CC>(g_xt + (size_t)r0*CC, w + (size_t)c0*CC, Ah, Al, Bh, Bl, acc, tid);

    const int lane = tid & 31, wp = tid >> 5;
    const int gid = lane >> 2, tig = lane & 3;
    const int wm = (wp & 3) * 32, wn = (wp >> 2) * 32;
#pragma unroll
    for (int ni = 0; ni < 4; ni++) {
        int col = c0 + wn + ni*8 + 2*tig;
        float sca = bg[col]   * rsqrtf(bv[col]   + 1e-5f);
        float scb = bg[col+1] * rsqrtf(bv[col+1] + 1e-5f);
        float sha = bbta[col]   - bm[col]  *sca;
        float shb = bbta[col+1] - bm[col+1]*scb;
        float bia = bias[col], bib = bias[col+1];
#pragma unroll
        for (int mi = 0; mi < 2; mi++) {
            int r_lo = r0 + wm + mi*16 + gid;
#pragma unroll
            for (int h = 0; h < 2; h++) {
                int r = r_lo + h*8;
                float2 v2;
                v2.x = (acc[mi][ni][2*h]   + bia)*sca + sha;
                v2.y = (acc[mi][ni][2*h+1] + bib)*scb + shb;
                *(float2*)(g_h + (size_t)r*CC + col) = v2;
            }
        }
    }
}

// ---------------------------------------------------------------------------
// Kernel 2: row squared norms of h.
__global__ void x2_kernel()
{
    int warp = (blockIdx.x*blockDim.x + threadIdx.x) >> 5;
    int lane = threadIdx.x & 31;
    if (warp >= MTOT) return;
    const float* r = g_h + (size_t)warp*CC;
    float s = 0.f;
    for (int c = lane; c < CC; c += 32) { float v = r[c]; s = fmaf(v, v, s); }
#pragma unroll
    for (int o = 16; o; o >>= 1) s += __shfl_xor_sync(0xffffffffu, s, o);
    if (!lane) g_x2[warp] = s;
}

// ---------------------------------------------------------------------------
// Kernel 3 (split-bf16, symmetric): dist[b][n][m] = x2[n]+x2[m]-2<h_n,h_m>.
// 128(n) x 64(m) tiles; compute only blocks with bj >= 2*bi; fill the rest
// via guarded transpose writes (each element written exactly once).
__global__ void __launch_bounds__(256) dist_kernel()
{
    __shared__ uint32_t Ah[8*SA], Al[8*SA], Bh[8*SB], Bl[8*SB];
    __shared__ float Os[64][129];
    const int b = blockIdx.z;
    int t = blockIdx.x;
    int bi = 0;
    while (t >= 16 - 2*bi) { t -= 16 - 2*bi; bi++; }
    const int bj = 2*bi + t;
    const int n0 = bi * 128;
    const int m0 = bj * 64;
    const int tid = threadIdx.x;
    const float* hb = g_h + (size_t)b*NN*CC;

    float acc[2][4][4];
#pragma unroll
    for (int mi = 0; mi < 2; mi++)
#pragma unroll
        for (int ni = 0; ni < 4; ni++)
#pragma unroll
            for (int q = 0; q < 4; q++) acc[mi][ni][q] = 0.f;

    bfs_gemm_tile<CC>(hb + (size_t)n0*CC, hb + (size_t)m0*CC, Ah, Al, Bh, Bl, acc, tid);

    float* db = g_dist + (size_t)b*NN*NN;
    const int lane = tid & 31, wp = tid >> 5;
    const int gid = lane >> 2, tig = lane & 3;
    const int wm = (wp & 3) * 32, wn = (wp >> 2) * 32;
#pragma unroll
    for (int ni = 0; ni < 4; ni++) {
        int cl = wn + ni*8 + 2*tig;
        float xa = g_x2[b*NN + m0 + cl];
        float xb2 = g_x2[b*NN + m0 + cl + 1];
#pragma unroll
        for (int mi = 0; mi < 2; mi++) {
            int rl_lo = wm + mi*16 + gid;
#pragma unroll
            for (int h = 0; h < 2; h++) {
                int rl = rl_lo + h*8;
                int n = n0 + rl;
                float xn = g_x2[b*NN + n];
                float2 v2;
                v2.x = xn + xa  - 2.f*acc[mi][ni][2*h];
                v2.y = xn + xb2 - 2.f*acc[mi][ni][2*h+1];
                *(float2*)(db + (size_t)n*NN + m0 + cl) = v2;    // direct tile
                Os[cl][rl]   = v2.x;                              // transpose stage
                Os[cl+1][rl] = v2.y;
            }
        }
    }
    __syncthreads();
    // transpose write: dist[m][n], skip positions already direct-covered
#pragma unroll
    for (int it = 0; it < 32; it++) {
        int e = tid + it*256;     // 8192 elements
        int il = e & 127;         // local n (fastest -> coalesced)
        int jl = e >> 7;          // local m
        int r = m0 + jl;
        int c = n0 + il;
        if ((c >> 6) < 2*(r >> 7))
            db[(size_t)r*NN + c] = Os[jl][il];
    }
}

// ---------------------------------------------------------------------------
// Kernel 4: top-9 smallest per row (tie -> lower index).
__global__ void topk_kernel()
{
    const int row = blockIdx.x;            // b*N + n
    const float* d = g_dist + (size_t)row * NN;
    const int t = threadIdx.x;             // 256 threads
    const int lane = t & 31, w = t >> 5;

    unsigned long long k[4];
#pragma unroll
    for (int j = 0; j < 4; j++) {
        float v = d[t + j*256];
        unsigned u = __float_as_uint(v);
        u = (u & 0x80000000u) ? ~u : (u | 0x80000000u);   // monotonic map
        k[j] = ((unsigned long long)u << 32) | (unsigned)(t + j*256);
    }
    unsigned long long lm = min(min(k[0], k[1]), min(k[2], k[3]));

    __shared__ unsigned long long swk[8];
    __shared__ unsigned long long sbest;

    for (int kp = 0; kp < KNN; kp++) {
        unsigned long long bkey = lm;
#pragma unroll
        for (int o = 16; o; o >>= 1) {
            unsigned long long ob = __shfl_down_sync(0xffffffffu, bkey, o);
            bkey = min(bkey, ob);
        }
        if (!lane) swk[w] = bkey;
        __syncthreads();
        if (w == 0) {
            unsigned long long rb = (lane < 8) ? swk[lane] : ~0ull;
#pragma unroll
            for (int o = 4; o; o >>= 1) {
                unsigned long long ob = __shfl_down_sync(0xffffffffu, rb, o);
                rb = min(rb, ob);
            }
            if (!lane) {
                sbest = rb;
                g_idx[row*KNN + kp] = (int)(rb & 0xffffffffu);
            }
        }
        __syncthreads();
        unsigned long long sel = sbest;
        int sidx = (int)(sel & 0xffffffffu);
        if ((sidx & 255) == t) {           // owner recomputes its cached min
            int jj = sidx >> 8;
            k[jj] = ~0ull;
            lm = min(min(k[0], k[1]), min(k[2], k[3]));
        }
    }
}

// ---------------------------------------------------------------------------
// Kernel 5: MRConv + interleave: m[2c]=h[c], m[2c+1]=max_j(h[idx_j,c]-h[n,c])
__global__ void mrconv_kernel()
{
    const int n = blockIdx.x, b = blockIdx.y, c = threadIdx.x;  // 256 threads
    const size_t rowb = (size_t)b*NN + n;
    __shared__ int sidx[KNN];
    if (c < KNN) sidx[c] = g_idx[rowb*KNN + c];
    __syncthreads();
    float v = g_h[rowb*CC + c];
    float mx = -INFINITY;
#pragma unroll
    for (int j = 0; j < KNN; j++) {
        int nb = sidx[j];
        mx = fmaxf(mx, g_h[((size_t)b*NN + nb)*CC + c] - v);
    }
    float* mo = g_m + rowb*2*CC;
    mo[2*c]   = v;
    mo[2*c+1] = mx;
}

// ---------------------------------------------------------------------------
// Kernel 6 (tf32 mma): g = GELU(BN2(GBN(gc_w @ m + gc_b)))
__global__ void __launch_bounds__(256) gc_kernel(
    const float* __restrict__ w, const float* __restrict__ bias,
    const float* __restrict__ g1g, const float* __restrict__ g1b,
    const float* __restrict__ g1m, const float* __restrict__ g1v,
    const float* __restrict__ g2g, const float* __restrict__ g2b,
    const float* __restrict__ g2m, const float* __restrict__ g2v)
{
    __shared__ uint32_t Ask[16*SA];
    __shared__ uint32_t Bsk[16*SB];
    const int r0 = blockIdx.x * 128;
    const int c0 = blockIdx.y * 64;
    const int tid = threadIdx.x;

    float acc[2][4][4];
#pragma unroll
    for (int mi = 0; mi < 2; mi++)
#pragma unroll
        for (int ni = 0; ni < 4; ni++)
#pragma unroll
            for (int q = 0; q < 4; q++) acc[mi][ni][q] = 0.f;

    tf32_gemm_tile<2*CC>(g_m + (size_t)r0*(2*CC), w + (size_t)c0*(2*CC), Ask, Bsk, acc, tid);

    const int lane = tid & 31, wp = tid >> 5;
    const int gid = lane >> 2, tig = lane & 3;
    const int wm = (wp & 3) * 32, wn = (wp >> 2) * 32;
#pragma unroll
    for (int ni = 0; ni < 4; ni++) {
        int col = c0 + wn + ni*8 + 2*tig;
        float s1a = g1g[col]   * rsqrtf(g1v[col]   + 1e-5f);
        float s1b = g1g[col+1] * rsqrtf(g1v[col+1] + 1e-5f);
        float t1a = g1b[col]   - g1m[col]  *s1a;
        float t1b = g1b[col+1] - g1m[col+1]*s1b;
        float s2a = g2g[col]   * rsqrtf(g2v[col]   + 1e-5f);
        float s2b = g2g[col+1] * rsqrtf(g2v[col+1] + 1e-5f);
        float t2a = g2b[col]   - g2m[col]  *s2a;
        float t2b = g2b[col+1] - g2m[col+1]*s2b;
        float bia = bias[col], bib = bias[col+1];
#pragma unroll
        for (int mi = 0; mi < 2; mi++) {
            int r_lo = r0 + wm + mi*16 + gid;
#pragma unroll
            for (int h = 0; h < 2; h++) {
                int r = r_lo + h*8;
                float ya = ((acc[mi][ni][2*h]   + bia)*s1a + t1a)*s2a + t2a;
                float yb = ((acc[mi][ni][2*h+1] + bib)*s1b + t1b)*s2b + t2b;
                ya = 0.5f * ya * (1.f + erff(ya * 0.70710678118654752440f));
                yb = 0.5f * yb * (1.f + erff(yb * 0.70710678118654752440f));
                float2 v2; v2.x = ya; v2.y = yb;
                *(float2*)(g_g + (size_t)r*HID + col) = v2;
            }
        }
    }
}

// ---------------------------------------------------------------------------
// Kernel 7 (tf32 mma): out = BN3(fc2_w @ g + fc2_b) + x, (B,C,N) layout via
// smem restage for coalesced transposed stores.
__global__ void __launch_bounds__(256) fc2_kernel(
    const float* __restrict__ w, const float* __restrict__ bias,
    const float* __restrict__ bg, const float* __restrict__ bbta,
    const float* __restrict__ bm, const float* __restrict__ bv,
    const float* __restrict__ x, float* __restrict__ out)
{
    __shared__ uint32_t Ask[16*SA];
    __shared__ uint32_t Bsk[16*SB];
    __shared__ float Os[128*65];
    const int r0 = blockIdx.x * 128;
    const int c0 = blockIdx.y * 64;
    const int tid = threadIdx.x;

    float acc[2][4][4];
#pragma unroll
    for (int mi = 0; mi < 2; mi++)
#pragma unroll
        for (int ni = 0; ni < 4; ni++)
#pragma unroll
            for (int q = 0; q < 4; q++) acc[mi][ni][q] = 0.f;

    tf32_gemm_tile<HID>(g_g + (size_t)r0*HID, w + (size_t)c0*HID, Ask, Bsk, acc, tid);

    const int lane = tid & 31, wp = tid >> 5;
    const int gid = lane >> 2, tig = lane & 3;
    const int wm = (wp & 3) * 32, wn = (wp >> 2) * 32;
#pragma unroll
    for (int ni = 0; ni < 4; ni++) {
        int cl = wn + ni*8 + 2*tig;
        int col = c0 + cl;
        float sca = bg[col]   * rsqrtf(bv[col]   + 1e-5f);
        float scb = bg[col+1] * rsqrtf(bv[col+1] + 1e-5f);
        float sha = bbta[col]   - bm[col]  *sca;
        float shb = bbta[col+1] - bm[col+1]*scb;
        float bia = bias[col], bib = bias[col+1];
#pragma unroll
        for (int mi = 0; mi < 2; mi++) {
            int rl_lo = wm + mi*16 + gid;
#pragma unroll
            for (int h = 0; h < 2; h++) {
                int rl = rl_lo + h*8;
                Os[rl*65 + cl]     = (acc[mi][ni][2*h]   + bia)*sca + sha;
                Os[rl*65 + cl + 1] = (acc[mi][ni][2*h+1] + bib)*scb + shb;
            }
        }
    }
    __syncthreads();
    const int b = r0 >> 10;
    const int nbase = r0 & 1023;
#pragma unroll
    for (int it = 0; it < 32; it++) {
        int e = tid + it*256;     // 8192 elements
        int nl = e & 127;
        int cl = e >> 7;
        size_t o = (size_t)b*CC*NN + (size_t)(c0 + cl)*NN + (nbase + nl);
        out[o] = Os[nl*65 + cl] + x[o];
    }
}

// ---------------------------------------------------------------------------
extern "C" void kernel_launch(void* const* d_in, const int* in_sizes, int n_in,
                              void* d_out, int out_size)
{
    const float* x     = (const float*)d_in[0];
    const float* fc1_w = (const float*)d_in[1];
    const float* fc1_b = (const float*)d_in[2];
    const float* bn1_g = (const float*)d_in[3];
    const float* bn1_b = (const float*)d_in[4];
    const float* bn1_m = (const float*)d_in[5];
    const float* bn1_v = (const float*)d_in[6];
    const float* gc_w  = (const float*)d_in[7];
    const float* gc_b  = (const float*)d_in[8];
    const float* gbn_g = (const float*)d_in[9];
    const float* gbn_b = (const float*)d_in[10];
    const float* gbn_m = (const float*)d_in[11];
    const float* gbn_v = (const float*)d_in[12];
    const float* bn2_g = (const float*)d_in[13];
    const float* bn2_b = (const float*)d_in[14];
    const float* bn2_m = (const float*)d_in[15];
    const float* bn2_v = (const float*)d_in[16];
    const float* fc2_w = (const float*)d_in[17];
    const float* fc2_b = (const float*)d_in[18];
    const float* bn3_g = (const float*)d_in[19];
    const float* bn3_b = (const float*)d_in[20];
    const float* bn3_m = (const float*)d_in[21];
    const float* bn3_v = (const float*)d_in[22];
    float* out = (float*)d_out;

    // 0) transpose x -> node-major
    {
        dim3 grid(NN/32, CC/32, BB);
        dim3 blk(32, 8);
        xt_kernel<<<grid, blk>>>(x);
    }
    // 1) fc1 + BN1 -> h (split-bf16 tensor cores, ~fp32 accurate)
    {
        dim3 grid(MTOT/128, CC/64);
        fc1_kernel<<<grid, 256>>>(fc1_w, fc1_b, bn1_g, bn1_b, bn1_m, bn1_v);
    }
    // 2) row norms
    x2_kernel<<<(MTOT*32)/256, 256>>>();
    // 3) pairwise distances (split-bf16, symmetric triangular blocks)
    {
        dim3 grid(72, 1, BB);
        dist_kernel<<<grid, 256>>>();
    }
    // 4) top-9 nearest per node
    topk_kernel<<<MTOT, 256>>>();
    // 5) MRConv + interleave
    {
        dim3 grid(NN, BB);
        mrconv_kernel<<<grid, 256>>>();
    }
    // 6) gc + gbn + bn2 + GELU (tf32 tensor cores)
    {
        dim3 grid(MTOT/128, HID/64);
        gc_kernel<<<grid, 256>>>(gc_w, gc_b, gbn_g, gbn_b, gbn_m, gbn_v,
                                 bn2_g, bn2_b, bn2_m, bn2_v);
    }
    // 7) fc2 + bn3 + residual (tf32 tensor cores)
    {
        dim3 grid(MTOT/128, CC/64);
        fc2_kernel<<<grid, 256>>>(fc2_w, fc2_b, bn3_g, bn3_b, bn3_m, bn3_v, x, out);
    }
}

// round 7
// speedup vs baseline: 2.7451x; 1.0853x over previous
#include <cuda_runtime.h>
#include <cuda_bf16.h>
#include <stdint.h>
#include <math.h>

// Problem constants
#define BB   16
#define CC   256
#define NN   1024
#define HID  512
#define KNN  9
#define MTOT (BB*NN)   // 16384

// smem strides (u32 words), % 32 == 8 -> conflict-free fragment LDS
#define SA 136
#define SB 72

// GEMM smem sub-buffer sizes (bytes)
#define BF_AH (8*SA*4)      // 4352
#define BF_AB (2*BF_AH)     // Ah+Al
#define BF_BH (8*SB*4)      // 2304
#define BF_GEMM (BF_AB + 2*BF_BH)          // 13312  (split-bf16 core)
#define TF_A (16*SA*4)      // 8704
#define TF_B (16*SB*4)      // 4608
#define TF_GEMM (TF_A + TF_B)              // 13312  (tf32 core)

// ---------------- scratch (static device globals; no allocations) ----------
__device__ float g_xt  [(size_t)MTOT*CC];       // x transposed to node-major
__device__ float g_h   [(size_t)MTOT*CC];       // node-major h
__device__ float g_x2  [MTOT];                  // row squared norms
__device__ float g_dist[(size_t)BB*NN*NN];      // per-batch distance matrices
__device__ int   g_idx [MTOT*KNN];              // knn indices (batch-local)
__device__ float g_m   [(size_t)MTOT*2*CC];     // interleaved [h, maxdiff]
__device__ float g_g   [(size_t)MTOT*HID];      // post-GELU activations

// ---------------------------------------------------------------------------
// mma helpers
__device__ __forceinline__ uint32_t f2tf32(float f){
    uint32_t u; asm("cvt.rna.tf32.f32 %0, %1;" : "=r"(u) : "f"(f)); return u;
}
__device__ __forceinline__ void mma_tf32(float* c,
    uint32_t a0, uint32_t a1, uint32_t a2, uint32_t a3, uint32_t b0, uint32_t b1)
{
    asm volatile("mma.sync.aligned.m16n8k8.row.col.f32.tf32.tf32.f32 "
        "{%0,%1,%2,%3}, {%4,%5,%6,%7}, {%8,%9}, {%0,%1,%2,%3};"
        : "+f"(c[0]), "+f"(c[1]), "+f"(c[2]), "+f"(c[3])
        : "r"(a0), "r"(a1), "r"(a2), "r"(a3), "r"(b0), "r"(b1));
}
__device__ __forceinline__ void mma_bf16(float* c,
    uint32_t a0, uint32_t a1, uint32_t a2, uint32_t a3, uint32_t b0, uint32_t b1)
{
    asm volatile("mma.sync.aligned.m16n8k16.row.col.f32.bf16.bf16.f32 "
        "{%0,%1,%2,%3}, {%4,%5,%6,%7}, {%8,%9}, {%0,%1,%2,%3};"
        : "+f"(c[0]), "+f"(c[1]), "+f"(c[2]), "+f"(c[3])
        : "r"(a0), "r"(a1), "r"(a2), "r"(a3), "r"(b0), "r"(b1));
}

// split two floats (consecutive k) into packed bf16x2 hi and lo words
__device__ __forceinline__ void splitpack(float x, float y, uint32_t& h, uint32_t& l){
    __nv_bfloat16 hx = __float2bfloat16(x);
    __nv_bfloat16 hy = __float2bfloat16(y);
    float rx = x - __bfloat162float(hx);
    float ry = y - __bfloat162float(hy);
    __nv_bfloat16 lx = __float2bfloat16(rx);
    __nv_bfloat16 ly = __float2bfloat16(ry);
    uint16_t hxb = *(uint16_t*)&hx, hyb = *(uint16_t*)&hy;
    uint16_t lxb = *(uint16_t*)&lx, lyb = *(uint16_t*)&ly;
    h = ((uint32_t)hyb << 16) | hxb;
    l = ((uint32_t)lyb << 16) | lxb;
}

// ---------------------------------------------------------------------------
// Split-bf16 (hi+lo, 3-pass) GEMM core, register-prefetch pipelined.
// Block tile 128x64, 256 threads, 8 warps x (32x32).
template<int K>
__device__ __forceinline__ void bfs_gemm_tile(
    const float* __restrict__ A, const float* __restrict__ B,
    uint32_t* Ah, uint32_t* Al, uint32_t* Bh, uint32_t* Bl,
    float acc[2][4][4], int tid)
{
    const int lane = tid & 31, w = tid >> 5;
    const int gid = lane >> 2, tig = lane & 3;
    const int wm = (w & 3) * 32, wn = (w >> 2) * 32;
    const int am = tid >> 1, ak2 = (tid & 1) * 4;  // A: 128 rows, 2 thr/row
    const int bn = tid >> 2, bk2 = (tid & 3) * 2;  // B: 64 rows, 4 thr/row

    const float* Ap = A + (size_t)am*K + ak2*2;
    const float* Bp = B + (size_t)bn*K + bk2*2;
    float4 a4a = *(const float4*)(Ap);
    float4 a4b = *(const float4*)(Ap + 4);
    float4 b4  = *(const float4*)(Bp);

    for (int k0 = 0; k0 < K; k0 += 16) {
        uint32_t h0,l0,h1,l1,h2,l2,h3,l3;
        splitpack(a4a.x, a4a.y, h0, l0);
        splitpack(a4a.z, a4a.w, h1, l1);
        splitpack(a4b.x, a4b.y, h2, l2);
        splitpack(a4b.z, a4b.w, h3, l3);
        Ah[(ak2+0)*SA + am] = h0; Al[(ak2+0)*SA + am] = l0;
        Ah[(ak2+1)*SA + am] = h1; Al[(ak2+1)*SA + am] = l1;
        Ah[(ak2+2)*SA + am] = h2; Al[(ak2+2)*SA + am] = l2;
        Ah[(ak2+3)*SA + am] = h3; Al[(ak2+3)*SA + am] = l3;
        uint32_t bh0,bl0,bh1,bl1;
        splitpack(b4.x, b4.y, bh0, bl0);
        splitpack(b4.z, b4.w, bh1, bl1);
        Bh[(bk2+0)*SB + bn] = bh0; Bl[(bk2+0)*SB + bn] = bl0;
        Bh[(bk2+1)*SB + bn] = bh1; Bl[(bk2+1)*SB + bn] = bl1;
        __syncthreads();
        if (k0 + 16 < K) {                       // prefetch next slab
            a4a = *(const float4*)(Ap + k0 + 16);
            a4b = *(const float4*)(Ap + k0 + 20);
            b4  = *(const float4*)(Bp + k0 + 16);
        }
        uint32_t ahf[2][4], alf[2][4], bhf[4][2], blf[4][2];
#pragma unroll
        for (int mi = 0; mi < 2; mi++) {
            int mo = wm + mi*16 + gid;
            ahf[mi][0] = Ah[ tig   *SA + mo];
            ahf[mi][1] = Ah[ tig   *SA + mo + 8];
            ahf[mi][2] = Ah[(tig+4)*SA + mo];
            ahf[mi][3] = Ah[(tig+4)*SA + mo + 8];
            alf[mi][0] = Al[ tig   *SA + mo];
            alf[mi][1] = Al[ tig   *SA + mo + 8];
            alf[mi][2] = Al[(tig+4)*SA + mo];
            alf[mi][3] = Al[(tig+4)*SA + mo + 8];
        }
#pragma unroll
        for (int ni = 0; ni < 4; ni++) {
            int no = wn + ni*8 + gid;
            bhf[ni][0] = Bh[ tig   *SB + no];
            bhf[ni][1] = Bh[(tig+4)*SB + no];
            blf[ni][0] = Bl[ tig   *SB + no];
            blf[ni][1] = Bl[(tig+4)*SB + no];
        }
#pragma unroll
        for (int mi = 0; mi < 2; mi++)
#pragma unroll
            for (int ni = 0; ni < 4; ni++) {
                mma_bf16(acc[mi][ni], ahf[mi][0], ahf[mi][1], ahf[mi][2], ahf[mi][3],
                         bhf[ni][0], bhf[ni][1]);
                mma_bf16(acc[mi][ni], ahf[mi][0], ahf[mi][1], ahf[mi][2], ahf[mi][3],
                         blf[ni][0], blf[ni][1]);
                mma_bf16(acc[mi][ni], alf[mi][0], alf[mi][1], alf[mi][2], alf[mi][3],
                         bhf[ni][0], bhf[ni][1]);
            }
        __syncthreads();
    }
}

// ---------------------------------------------------------------------------
// tf32 single-pass GEMM core (gc, fc2), register-prefetch pipelined.
template<int K>
__device__ __forceinline__ void tf32_gemm_tile(
    const float* __restrict__ A, const float* __restrict__ B,
    uint32_t* Ask, uint32_t* Bsk, float acc[2][4][4], int tid)
{
    const int lane = tid & 31, w = tid >> 5;
    const int gid = lane >> 2, tig = lane & 3;
    const int wm = (w & 3) * 32, wn = (w >> 2) * 32;
    const int am = tid >> 1, ak = (tid & 1) * 8;
    const int bn = tid >> 2, bk = (tid & 3) * 4;

    const float* Ap = A + (size_t)am*K + ak;
    const float* Bp = B + (size_t)bn*K + bk;
    float4 a4a = *(const float4*)(Ap);
    float4 a4b = *(const float4*)(Ap + 4);
    float4 b4  = *(const float4*)(Bp);

    for (int k0 = 0; k0 < K; k0 += 16) {
        Ask[(ak+0)*SA + am] = f2tf32(a4a.x);
        Ask[(ak+1)*SA + am] = f2tf32(a4a.y);
        Ask[(ak+2)*SA + am] = f2tf32(a4a.z);
        Ask[(ak+3)*SA + am] = f2tf32(a4a.w);
        Ask[(ak+4)*SA + am] = f2tf32(a4b.x);
        Ask[(ak+5)*SA + am] = f2tf32(a4b.y);
        Ask[(ak+6)*SA + am] = f2tf32(a4b.z);
        Ask[(ak+7)*SA + am] = f2tf32(a4b.w);
        Bsk[(bk+0)*SB + bn] = f2tf32(b4.x);
        Bsk[(bk+1)*SB + bn] = f2tf32(b4.y);
        Bsk[(bk+2)*SB + bn] = f2tf32(b4.z);
        Bsk[(bk+3)*SB + bn] = f2tf32(b4.w);
        __syncthreads();
        if (k0 + 16 < K) {
            a4a = *(const float4*)(Ap + k0 + 16);
            a4b = *(const float4*)(Ap + k0 + 20);
            b4  = *(const float4*)(Bp + k0 + 16);
        }
#pragma unroll
        for (int ks = 0; ks < 16; ks += 8) {
            uint32_t af[2][4], bf[4][2];
#pragma unroll
            for (int mi = 0; mi < 2; mi++) {
                int mo = wm + mi*16 + gid;
                af[mi][0] = Ask[(ks+tig  )*SA + mo];
                af[mi][1] = Ask[(ks+tig  )*SA + mo + 8];
                af[mi][2] = Ask[(ks+tig+4)*SA + mo];
                af[mi][3] = Ask[(ks+tig+4)*SA + mo + 8];
            }
#pragma unroll
            for (int ni = 0; ni < 4; ni++) {
                int no = wn + ni*8 + gid;
                bf[ni][0] = Bsk[(ks+tig  )*SB + no];
                bf[ni][1] = Bsk[(ks+tig+4)*SB + no];
            }
#pragma unroll
            for (int mi = 0; mi < 2; mi++)
#pragma unroll
                for (int ni = 0; ni < 4; ni++)
                    mma_tf32(acc[mi][ni], af[mi][0], af[mi][1], af[mi][2], af[mi][3],
                             bf[ni][0], bf[ni][1]);
        }
        __syncthreads();
    }
}

// ---------------------------------------------------------------------------
// Kernel 0: transpose x (B,C,N) -> g_xt node-major [(b*N+n)*C + c]
__global__ void xt_kernel(const float* __restrict__ x)
{
    __shared__ float t[32][33];
    const int b = blockIdx.z;
    const int n0 = blockIdx.x*32, c0 = blockIdx.y*32;
    const int tx = threadIdx.x, ty = threadIdx.y;   // 32 x 8
    const float* xb = x + (size_t)b*CC*NN;
#pragma unroll
    for (int i = 0; i < 4; i++)
        t[ty+8*i][tx] = xb[(size_t)(c0+ty+8*i)*NN + n0+tx];
    __syncthreads();
#pragma unroll
    for (int i = 0; i < 4; i++)
        g_xt[(size_t)(b*NN + n0 + ty+8*i)*CC + c0 + tx] = t[tx][ty+8*i];
}

// ---------------------------------------------------------------------------
// Kernel 1 (split-bf16): h = BN1(fc1_w @ xT + fc1_b), node-major output.
__global__ void __launch_bounds__(256) fc1_kernel(
    const float* __restrict__ w, const float* __restrict__ bias,
    const float* __restrict__ bg, const float* __restrict__ bbta,
    const float* __restrict__ bm, const float* __restrict__ bv)
{
    __shared__ __align__(16) char sbuf[BF_GEMM];
    uint32_t* Ah = (uint32_t*)sbuf;
    uint32_t* Al = (uint32_t*)(sbuf + BF_AH);
    uint32_t* Bh = (uint32_t*)(sbuf + BF_AB);
    uint32_t* Bl = (uint32_t*)(sbuf + BF_AB + BF_BH);
    const int r0 = blockIdx.x * 128;
    const int c0 = blockIdx.y * 64;
    const int tid = threadIdx.x;

    float acc[2][4][4];
#pragma unroll
    for (int mi = 0; mi < 2; mi++)
#pragma unroll
        for (int ni = 0; ni < 4; ni++)
#pragma unroll
            for (int q = 0; q < 4; q++) acc[mi][ni][q] = 0.f;

    bfs_gemm_tile<CC>(g_xt + (size_t)r0*CC, w + (size_t)c0*CC, Ah, Al, Bh, Bl, acc, tid);

    const int lane = tid & 31, wp = tid >> 5;
    const int gid = lane >> 2, tig = lane & 3;
    const int wm = (wp & 3) * 32, wn = (wp >> 2) * 32;
#pragma unroll
    for (int ni = 0; ni < 4; ni++) {
        int col = c0 + wn + ni*8 + 2*tig;
        float sca = bg[col]   * rsqrtf(bv[col]   + 1e-5f);
        float scb = bg[col+1] * rsqrtf(bv[col+1] + 1e-5f);
        float sha = bbta[col]   - bm[col]  *sca;
        float shb = bbta[col+1] - bm[col+1]*scb;
        float bia = bias[col], bib = bias[col+1];
#pragma unroll
        for (int mi = 0; mi < 2; mi++) {
            int r_lo = r0 + wm + mi*16 + gid;
#pragma unroll
            for (int h = 0; h < 2; h++) {
                int r = r_lo + h*8;
                float2 v2;
                v2.x = (acc[mi][ni][2*h]   + bia)*sca + sha;
                v2.y = (acc[mi][ni][2*h+1] + bib)*scb + shb;
                *(float2*)(g_h + (size_t)r*CC + col) = v2;
            }
        }
    }
}

// ---------------------------------------------------------------------------
// Kernel 2: row squared norms of h.
__global__ void x2_kernel()
{
    int warp = (blockIdx.x*blockDim.x + threadIdx.x) >> 5;
    int lane = threadIdx.x & 31;
    if (warp >= MTOT) return;
    const float* r = g_h + (size_t)warp*CC;
    float s = 0.f;
    for (int c = lane; c < CC; c += 32) { float v = r[c]; s = fmaf(v, v, s); }
#pragma unroll
    for (int o = 16; o; o >>= 1) s += __shfl_xor_sync(0xffffffffu, s, o);
    if (!lane) g_x2[warp] = s;
}

// ---------------------------------------------------------------------------
// Kernel 3 (split-bf16, symmetric): dist[b][n][m] = x2[n]+x2[m]-2<h_n,h_m>.
// 128(n) x 64(m) tiles; compute only blocks with bj >= 2*bi; fill the rest
// via guarded transpose writes. GEMM smem aliased with transpose stage.
__global__ void __launch_bounds__(256) dist_kernel()
{
    __shared__ __align__(16) char sbuf[64*129*4];   // 33024 B, covers both uses
    uint32_t* Ah = (uint32_t*)sbuf;
    uint32_t* Al = (uint32_t*)(sbuf + BF_AH);
    uint32_t* Bh = (uint32_t*)(sbuf + BF_AB);
    uint32_t* Bl = (uint32_t*)(sbuf + BF_AB + BF_BH);
    float (*Os)[129] = (float(*)[129])sbuf;
    const int b = blockIdx.z;
    int t = blockIdx.x;
    int bi = 0;
    while (t >= 16 - 2*bi) { t -= 16 - 2*bi; bi++; }
    const int bj = 2*bi + t;
    const int n0 = bi * 128;
    const int m0 = bj * 64;
    const int tid = threadIdx.x;
    const float* hb = g_h + (size_t)b*NN*CC;

    float acc[2][4][4];
#pragma unroll
    for (int mi = 0; mi < 2; mi++)
#pragma unroll
        for (int ni = 0; ni < 4; ni++)
#pragma unroll
            for (int q = 0; q < 4; q++) acc[mi][ni][q] = 0.f;

    bfs_gemm_tile<CC>(hb + (size_t)n0*CC, hb + (size_t)m0*CC, Ah, Al, Bh, Bl, acc, tid);

    float* db = g_dist + (size_t)b*NN*NN;
    const int lane = tid & 31, wp = tid >> 5;
    const int gid = lane >> 2, tig = lane & 3;
    const int wm = (wp & 3) * 32, wn = (wp >> 2) * 32;
#pragma unroll
    for (int ni = 0; ni < 4; ni++) {
        int cl = wn + ni*8 + 2*tig;
        float xa = g_x2[b*NN + m0 + cl];
        float xb2 = g_x2[b*NN + m0 + cl + 1];
#pragma unroll
        for (int mi = 0; mi < 2; mi++) {
            int rl_lo = wm + mi*16 + gid;
#pragma unroll
            for (int h = 0; h < 2; h++) {
                int rl = rl_lo + h*8;
                int n = n0 + rl;
                float xn = g_x2[b*NN + n];
                float2 v2;
                v2.x = xn + xa  - 2.f*acc[mi][ni][2*h];
                v2.y = xn + xb2 - 2.f*acc[mi][ni][2*h+1];
                *(float2*)(db + (size_t)n*NN + m0 + cl) = v2;    // direct tile
                Os[cl][rl]   = v2.x;                              // transpose stage
                Os[cl+1][rl] = v2.y;
            }
        }
    }
    __syncthreads();
    // transpose write: dist[m][n], skip positions already direct-covered
#pragma unroll
    for (int it = 0; it < 32; it++) {
        int e = tid + it*256;     // 8192 elements
        int il = e & 127;         // local n (fastest -> coalesced)
        int jl = e >> 7;          // local m
        int r = m0 + jl;
        int c = n0 + il;
        if ((c >> 6) < 2*(r >> 7))
            db[(size_t)r*NN + c] = Os[jl][il];
    }
}

// ---------------------------------------------------------------------------
// Kernel 4: top-9 smallest per row (tie -> lower index).
// One warp per row; 32 values/lane in registers; no smem, no block syncs.
__global__ void __launch_bounds__(256) topk_kernel()
{
    const int w = threadIdx.x >> 5, lane = threadIdx.x & 31;
    const int row = blockIdx.x*8 + w;                // 8 warps/block
    const float* d = g_dist + (size_t)row * NN;

    float v[32];
#pragma unroll
    for (int j = 0; j < 32; j++) v[j] = d[lane + j*32];

    // local min, tie -> lowest j (=> lowest index lane+j*32 within this lane)
    float bv = v[0]; int bj = 0;
#pragma unroll
    for (int j = 1; j < 32; j++) if (v[j] < bv) { bv = v[j]; bj = j; }

    for (int kp = 0; kp < KNN; kp++) {
        unsigned u = __float_as_uint(bv);
        u = (u & 0x80000000u) ? ~u : (u | 0x80000000u);   // monotonic map
        unsigned long long key =
            ((unsigned long long)u << 32) | (unsigned)(lane + (bj << 5));
#pragma unroll
        for (int o = 16; o; o >>= 1)
            key = min(key, __shfl_xor_sync(0xffffffffu, key, o));
        int sidx = (int)(key & 0xffffffffu);
        if (!lane) g_idx[row*KNN + kp] = sidx;
        if ((sidx & 31) == lane) {         // owner removes + rescans
            int jr = sidx >> 5;
#pragma unroll
            for (int j = 0; j < 32; j++) if (j == jr) v[j] = INFINITY;
            bv = v[0]; bj = 0;
#pragma unroll
            for (int j = 1; j < 32; j++) if (v[j] < bv) { bv = v[j]; bj = j; }
        }
    }
}

// ---------------------------------------------------------------------------
// Kernel 5: MRConv + interleave: m[2c]=h[c], m[2c+1]=max_j(h[idx_j,c]-h[n,c])
__global__ void mrconv_kernel()
{
    const int n = blockIdx.x, b = blockIdx.y, c = threadIdx.x;  // 256 threads
    const size_t rowb = (size_t)b*NN + n;
    __shared__ int sidx[KNN];
    if (c < KNN) sidx[c] = g_idx[rowb*KNN + c];
    __syncthreads();
    float v = g_h[rowb*CC + c];
    float mx = -INFINITY;
#pragma unroll
    for (int j = 0; j < KNN; j++) {
        int nb = sidx[j];
        mx = fmaxf(mx, g_h[((size_t)b*NN + nb)*CC + c] - v);
    }
    float* mo = g_m + rowb*2*CC;
    mo[2*c]   = v;
    mo[2*c+1] = mx;
}

// ---------------------------------------------------------------------------
// Kernel 6 (tf32 mma): g = GELU(BN2(GBN(gc_w @ m + gc_b)))
__global__ void __launch_bounds__(256) gc_kernel(
    const float* __restrict__ w, const float* __restrict__ bias,
    const float* __restrict__ g1g, const float* __restrict__ g1b,
    const float* __restrict__ g1m, const float* __restrict__ g1v,
    const float* __restrict__ g2g, const float* __restrict__ g2b,
    const float* __restrict__ g2m, const float* __restrict__ g2v)
{
    __shared__ __align__(16) char sbuf[TF_GEMM];
    uint32_t* Ask = (uint32_t*)sbuf;
    uint32_t* Bsk = (uint32_t*)(sbuf + TF_A);
    const int r0 = blockIdx.x * 128;
    const int c0 = blockIdx.y * 64;
    const int tid = threadIdx.x;

    float acc[2][4][4];
#pragma unroll
    for (int mi = 0; mi < 2; mi++)
#pragma unroll
        for (int ni = 0; ni < 4; ni++)
#pragma unroll
            for (int q = 0; q < 4; q++) acc[mi][ni][q] = 0.f;

    tf32_gemm_tile<2*CC>(g_m + (size_t)r0*(2*CC), w + (size_t)c0*(2*CC), Ask, Bsk, acc, tid);

    const int lane = tid & 31, wp = tid >> 5;
    const int gid = lane >> 2, tig = lane & 3;
    const int wm = (wp & 3) * 32, wn = (wp >> 2) * 32;
#pragma unroll
    for (int ni = 0; ni < 4; ni++) {
        int col = c0 + wn + ni*8 + 2*tig;
        float s1a = g1g[col]   * rsqrtf(g1v[col]   + 1e-5f);
        float s1b = g1g[col+1] * rsqrtf(g1v[col+1] + 1e-5f);
        float t1a = g1b[col]   - g1m[col]  *s1a;
        float t1b = g1b[col+1] - g1m[col+1]*s1b;
        float s2a = g2g[col]   * rsqrtf(g2v[col]   + 1e-5f);
        float s2b = g2g[col+1] * rsqrtf(g2v[col+1] + 1e-5f);
        float t2a = g2b[col]   - g2m[col]  *s2a;
        float t2b = g2b[col+1] - g2m[col+1]*s2b;
        float bia = bias[col], bib = bias[col+1];
#pragma unroll
        for (int mi = 0; mi < 2; mi++) {
            int r_lo = r0 + wm + mi*16 + gid;
#pragma unroll
            for (int h = 0; h < 2; h++) {
                int r = r_lo + h*8;
                float ya = ((acc[mi][ni][2*h]   + bia)*s1a + t1a)*s2a + t2a;
                float yb = ((acc[mi][ni][2*h+1] + bib)*s1b + t1b)*s2b + t2b;
                ya = 0.5f * ya * (1.f + erff(ya * 0.70710678118654752440f));
                yb = 0.5f * yb * (1.f + erff(yb * 0.70710678118654752440f));
                float2 v2; v2.x = ya; v2.y = yb;
                *(float2*)(g_g + (size_t)r*HID + col) = v2;
            }
        }
    }
}

// ---------------------------------------------------------------------------
// Kernel 7 (tf32 mma): out = BN3(fc2_w @ g + fc2_b) + x, (B,C,N) layout via
// smem restage (aliased with GEMM smem) for coalesced transposed stores.
__global__ void __launch_bounds__(256) fc2_kernel(
    const float* __restrict__ w, const float* __restrict__ bias,
    const float* __restrict__ bg, const float* __restrict__ bbta,
    const float* __restrict__ bm, const float* __restrict__ bv,
    const float* __restrict__ x, float* __restrict__ out)
{
    __shared__ __align__(16) char sbuf[128*65*4];   // 33280 B, covers both uses
    uint32_t* Ask = (uint32_t*)sbuf;
    uint32_t* Bsk = (uint32_t*)(sbuf + TF_A);
    float* Os = (float*)sbuf;
    const int r0 = blockIdx.x * 128;
    const int c0 = blockIdx.y * 64;
    const int tid = threadIdx.x;

    float acc[2][4][4];
#pragma unroll
    for (int mi = 0; mi < 2; mi++)
#pragma unroll
        for (int ni = 0; ni < 4; ni++)
#pragma unroll
            for (int q = 0; q < 4; q++) acc[mi][ni][q] = 0.f;

    tf32_gemm_tile<HID>(g_g + (size_t)r0*HID, w + (size_t)c0*HID, Ask, Bsk, acc, tid);
    __syncthreads();   // GEMM smem dead; safe to reuse as Os

    const int lane = tid & 31, wp = tid >> 5;
    const int gid = lane >> 2, tig = lane & 3;
    const int wm = (wp & 3) * 32, wn = (wp >> 2) * 32;
#pragma unroll
    for (int ni = 0; ni < 4; ni++) {
        int cl = wn + ni*8 + 2*tig;
        int col = c0 + cl;
        float sca = bg[col]   * rsqrtf(bv[col]   + 1e-5f);
        float scb = bg[col+1] * rsqrtf(bv[col+1] + 1e-5f);
        float sha = bbta[col]   - bm[col]  *sca;
        float shb = bbta[col+1] - bm[col+1]*scb;
        float bia = bias[col], bib = bias[col+1];
#pragma unroll
        for (int mi = 0; mi < 2; mi++) {
            int rl_lo = wm + mi*16 + gid;
#pragma unroll
            for (int h = 0; h < 2; h++) {
                int rl = rl_lo + h*8;
                Os[rl*65 + cl]     = (acc[mi][ni][2*h]   + bia)*sca + sha;
                Os[rl*65 + cl + 1] = (acc[mi][ni][2*h+1] + bib)*scb + shb;
            }
        }
    }
    __syncthreads();
    const int b = r0 >> 10;
    const int nbase = r0 & 1023;
#pragma unroll
    for (int it = 0; it < 32; it++) {
        int e = tid + it*256;     // 8192 elements
        int nl = e & 127;
        int cl = e >> 7;
        size_t o = (size_t)b*CC*NN + (size_t)(c0 + cl)*NN + (nbase + nl);
        out[o] = Os[nl*65 + cl] + x[o];
    }
}

// ---------------------------------------------------------------------------
extern "C" void kernel_launch(void* const* d_in, const int* in_sizes, int n_in,
                              void* d_out, int out_size)
{
    const float* x     = (const float*)d_in[0];
    const float* fc1_w = (const float*)d_in[1];
    const float* fc1_b = (const float*)d_in[2];
    const float* bn1_g = (const float*)d_in[3];
    const float* bn1_b = (const float*)d_in[4];
    const float* bn1_m = (const float*)d_in[5];
    const float* bn1_v = (const float*)d_in[6];
    const float* gc_w  = (const float*)d_in[7];
    const float* gc_b  = (const float*)d_in[8];
    const float* gbn_g = (const float*)d_in[9];
    const float* gbn_b = (const float*)d_in[10];
    const float* gbn_m = (const float*)d_in[11];
    const float* gbn_v = (const float*)d_in[12];
    const float* bn2_g = (const float*)d_in[13];
    const float* bn2_b = (const float*)d_in[14];
    const float* bn2_m = (const float*)d_in[15];
    const float* bn2_v = (const float*)d_in[16];
    const float* fc2_w = (const float*)d_in[17];
    const float* fc2_b = (const float*)d_in[18];
    const float* bn3_g = (const float*)d_in[19];
    const float* bn3_b = (const float*)d_in[20];
    const float* bn3_m = (const float*)d_in[21];
    const float* bn3_v = (const float*)d_in[22];
    float* out = (float*)d_out;

    // 0) transpose x -> node-major
    {
        dim3 grid(NN/32, CC/32, BB);
        dim3 blk(32, 8);
        xt_kernel<<<grid, blk>>>(x);
    }
    // 1) fc1 + BN1 -> h (split-bf16 tensor cores, ~fp32 accurate)
    {
        dim3 grid(MTOT/128, CC/64);
        fc1_kernel<<<grid, 256>>>(fc1_w, fc1_b, bn1_g, bn1_b, bn1_m, bn1_v);
    }
    // 2) row norms
    x2_kernel<<<(MTOT*32)/256, 256>>>();
    // 3) pairwise distances (split-bf16, symmetric triangular blocks)
    {
        dim3 grid(72, 1, BB);
        dist_kernel<<<grid, 256>>>();
    }
    // 4) top-9 nearest per node (warp per row)
    topk_kernel<<<MTOT/8, 256>>>();
    // 5) MRConv + interleave
    {
        dim3 grid(NN, BB);
        mrconv_kernel<<<grid, 256>>>();
    }
    // 6) gc + gbn + bn2 + GELU (tf32 tensor cores)
    {
        dim3 grid(MTOT/128, HID/64);
        gc_kernel<<<grid, 256>>>(gc_w, gc_b, gbn_g, gbn_b, gbn_m, gbn_v,
                                 bn2_g, bn2_b, bn2_m, bn2_v);
    }
    // 7) fc2 + bn3 + residual (tf32 tensor cores)
    {
        dim3 grid(MTOT/128, CC/64);
        fc2_kernel<<<grid, 256>>>(fc2_w, fc2_b, bn3_g, bn3_b, bn3_m, bn3_v, x, out);
    }
}